// round 12
// baseline (speedup 1.0000x reference)
#include <cuda_runtime.h>
#include <cuda_fp16.h>
#include <math.h>
#include <stdint.h>

// Problem constants
#define BB      16
#define GRID_D  1024
#define SEQ_D   1024
#define POS_D   512
#define NH      16
#define HEAD    64
#define LQ      1024
#define TKV     256
#define MULT    4
#define EPSF    1e-5f

// ---------------- scratch (static device memory) ---------------
__device__ __half g_gridh[(size_t)BB * TKV * GRID_D];
__device__ float  g_Kpre[(size_t)BB * TKV * SEQ_D];
__device__ __half g_Kn  [(size_t)BB * TKV * SEQ_D];
__device__ float  g_V   [(size_t)BB * TKV * SEQ_D];
__device__ __half g_qn  [(size_t)BB * LQ * POS_D];
__device__ float  g_Q   [(size_t)BB * LQ * SEQ_D];
__device__ __half g_attn[(size_t)BB * LQ * SEQ_D];
__device__ float  g_x   [(size_t)BB * LQ * SEQ_D];
__device__ __half g_xn  [(size_t)BB * LQ * SEQ_D];
__device__ __half g_h   [(size_t)BB * LQ * MULT * SEQ_D];
__device__ __half g_WkT [(size_t)SEQ_D * GRID_D];
__device__ __half g_WvT [(size_t)SEQ_D * GRID_D];
__device__ __half g_WqT [(size_t)SEQ_D * POS_D];
__device__ __half g_WoT [(size_t)SEQ_D * SEQ_D];
__device__ __half g_W1T [(size_t)MULT * SEQ_D * SEQ_D];
__device__ __half g_W2T [(size_t)SEQ_D * MULT * SEQ_D];
__device__ __half g_VT  [(size_t)BB * NH * HEAD * TKV];

// ---------------- helpers ----------------
__device__ __forceinline__ float gelu_f(float v) {
    float v3 = v * v * v;
    return 0.5f * v * (1.0f + tanhf(0.7978845608028654f * (v + 0.044715f * v3)));
}
__device__ __forceinline__ uint32_t sptr(const void* p) {
    uint32_t a;
    asm("{ .reg .u64 t; cvta.to.shared.u64 t, %1; cvt.u32.u64 %0, t; }" : "=r"(a) : "l"(p));
    return a;
}
__device__ __forceinline__ uint32_t pack2(float a, float b) {
    __half2 h = __float22half2_rn(make_float2(a, b));
    return *reinterpret_cast<uint32_t*>(&h);
}

#define CP_ASYNC16(dst, src) \
    asm volatile("cp.async.cg.shared.global [%0], [%1], 16;" \
                 :: "r"(dst), "l"(src) : "memory")
#define CP_COMMIT() asm volatile("cp.async.commit_group;" ::: "memory")
#define CP_WAIT0()  asm volatile("cp.async.wait_group 0;" ::: "memory")

#define LDMX4(r0, r1, r2, r3, addr) \
    asm volatile("ldmatrix.sync.aligned.m8n8.x4.shared.b16 {%0,%1,%2,%3}, [%4];" \
                 : "=r"(r0), "=r"(r1), "=r"(r2), "=r"(r3) : "r"(addr))

#define MMA16816(d, a, b) \
    asm volatile("mma.sync.aligned.m16n8k16.row.col.f32.f16.f16.f32 " \
                 "{%0,%1,%2,%3}, {%4,%5,%6,%7}, {%8,%9}, {%0,%1,%2,%3};" \
                 : "+f"((d)[0]), "+f"((d)[1]), "+f"((d)[2]), "+f"((d)[3]) \
                 : "r"((a)[0]), "r"((a)[1]), "r"((a)[2]), "r"((a)[3]), \
                   "r"((b)[0]), "r"((b)[1]))

enum { EPI_NONE = 0, EPI_RESID = 1, EPI_GELU_BIAS = 2, EPI_BIAS_RESID = 3 };

// =================================================================
// fp16 tensor-core GEMM (NT): C[M,N] = alpha * A[M,K] @ BT[N,K]^T (+epi)
// BM=128, BN=256, BK=32; 8 warps of 64x64; 2-stage cp.async pipeline
// (round-9-proven control flow; only tile geometry changed).
// Dynamic SMEM: 2 bufs x (A 128x40 + B 256x40) halves = 61440 B.
// =================================================================
#define GH_BM 128
#define GH_BN 256
#define GH_BK 32
#define GH_STR 40
#define GH_ABUF (GH_BM * GH_STR)            // halves per A buffer
#define GH_BBUF (GH_BN * GH_STR)            // halves per B buffer
#define GH_BOFF (2 * GH_ABUF)               // B region start (halves)
#define GH_SMEM ((2 * (GH_ABUF + GH_BBUF)) * 2)

template <typename TC, int EPI>
__global__ __launch_bounds__(256, 1)
void gemm_h(const __half* __restrict__ A, const __half* __restrict__ BT,
            const float* __restrict__ bias, const float* __restrict__ res,
            TC* __restrict__ C,
            int M, int N, int K, int lda, int ldb, int ldc, float alpha)
{
    extern __shared__ __half gsm[];
    const int tid  = threadIdx.x;
    const int lane = tid & 31;
    const int warp = tid >> 5;
    const int wm   = warp >> 2;          // 0..1
    const int wn   = warp & 3;           // 0..3
    const int m0   = blockIdx.y * GH_BM;
    const int n0   = blockIdx.x * GH_BN;

    float acc[4][8][4];
#pragma unroll
    for (int mt = 0; mt < 4; mt++)
#pragma unroll
        for (int nt = 0; nt < 8; nt++)
#pragma unroll
            for (int j = 0; j < 4; j++) acc[mt][nt][j] = 0.0f;

    auto issue = [&](int buf, int k0) {
        __half* As = gsm + buf * GH_ABUF;
        __half* Bs = gsm + GH_BOFF + buf * GH_BBUF;
#pragma unroll
        for (int i = 0; i < 2; i++) {              // A: 512 segs
            int s = tid + i * 256, r = s >> 2, cs = s & 3;
            CP_ASYNC16(sptr(As + r * GH_STR + cs * 8),
                       A + (size_t)(m0 + r) * lda + k0 + cs * 8);
        }
#pragma unroll
        for (int i = 0; i < 4; i++) {              // B: 1024 segs
            int s = tid + i * 256, r = s >> 2, cs = s & 3;
            CP_ASYNC16(sptr(Bs + r * GH_STR + cs * 8),
                       BT + (size_t)(n0 + r) * ldb + k0 + cs * 8);
        }
        CP_COMMIT();
    };

    const int lr = lane & 15;
    const int lc = lane >> 4;

    auto compute = [&](int buf) {
        const __half* As = gsm + buf * GH_ABUF;
        const __half* Bs = gsm + GH_BOFF + buf * GH_BBUF;
#pragma unroll
        for (int ks = 0; ks < 2; ks++) {
            uint32_t af[4][4];
#pragma unroll
            for (int mt = 0; mt < 4; mt++) {
                uint32_t ad = sptr(As + (wm * 64 + mt * 16 + lr) * GH_STR
                                      + ks * 16 + lc * 8);
                LDMX4(af[mt][0], af[mt][1], af[mt][2], af[mt][3], ad);
            }
            uint32_t bf[8][2];
#pragma unroll
            for (int np = 0; np < 4; np++) {
                uint32_t r0, r1, r2, r3;
                uint32_t bd = sptr(Bs + (wn * 64 + np * 16 + lr) * GH_STR
                                      + ks * 16 + lc * 8);
                LDMX4(r0, r1, r2, r3, bd);
                bf[np * 2 + 0][0] = r0; bf[np * 2 + 0][1] = r2;
                bf[np * 2 + 1][0] = r1; bf[np * 2 + 1][1] = r3;
            }
#pragma unroll
            for (int mt = 0; mt < 4; mt++)
#pragma unroll
                for (int nt = 0; nt < 8; nt++)
                    MMA16816(acc[mt][nt], af[mt], bf[nt]);
        }
    };

    const int nk = K / GH_BK;
    issue(0, 0);
    for (int it = 0; it < nk; ++it) {
        const int cur = it & 1;
        CP_WAIT0();
        __syncthreads();
        if (it + 1 < nk) issue(cur ^ 1, (it + 1) * GH_BK);
        compute(cur);
    }

    const int g4 = lane >> 2, t4 = lane & 3;
#pragma unroll
    for (int mt = 0; mt < 4; mt++) {
#pragma unroll
        for (int nt = 0; nt < 8; nt++) {
            int r = m0 + wm * 64 + mt * 16 + g4;
            int c = n0 + wn * 64 + nt * 8 + 2 * t4;
#pragma unroll
            for (int half = 0; half < 2; half++) {
                int rr = r + half * 8;
                float2 v = make_float2(acc[mt][nt][half * 2 + 0] * alpha,
                                       acc[mt][nt][half * 2 + 1] * alpha);
                if (EPI == EPI_GELU_BIAS) {
                    float2 bv = *(const float2*)(bias + c);
                    v.x = gelu_f(v.x + bv.x);
                    v.y = gelu_f(v.y + bv.y);
                } else if (EPI == EPI_RESID) {
                    float2 rv = *(const float2*)(res + (size_t)rr * ldc + c);
                    v.x += rv.x; v.y += rv.y;
                } else if (EPI == EPI_BIAS_RESID) {
                    float2 bv = *(const float2*)(bias + c);
                    float2 rv = *(const float2*)(res + (size_t)rr * ldc + c);
                    v.x += bv.x + rv.x; v.y += bv.y + rv.y;
                }
                if (sizeof(TC) == 4) {
                    *(float2*)((float*)(void*)C + (size_t)rr * ldc + c) = v;
                } else {
                    __half2 h = __float22half2_rn(v);
                    *(__half2*)((__half*)(void*)C + (size_t)rr * ldc + c) = h;
                }
            }
        }
    }
}

// =================================================================
// Fused attention (unchanged from round 9)
// =================================================================
#define FA_QS_OFF 0
#define FA_KS_OFF (128 * 72)
#define FA_VS_OFF (128 * 72 + 256 * 72)
#define FA_SMEM   ((128 * 72 + 256 * 72 + 64 * 264) * 2)

__global__ __launch_bounds__(256, 1)
void fused_attn(const float* __restrict__ Q, const __half* __restrict__ Kn,
                const __half* __restrict__ VT, __half* __restrict__ attn)
{
    extern __shared__ __half fsm[];
    __half* Qs = fsm + FA_QS_OFF;
    __half* Ks = fsm + FA_KS_OFF;
    __half* Vs = fsm + FA_VS_OFF;

    const int tid  = threadIdx.x;
    const int lane = tid & 31;
    const int warp = tid >> 5;
    const int q0   = blockIdx.x * 128;
    const int bh   = blockIdx.y;
    const int b    = bh >> 4;
    const int h    = bh & 15;

    const float*  Qg = Q  + ((size_t)b * LQ + q0) * SEQ_D + h * HEAD;
    const __half* Kg = Kn + (size_t)b * TKV * SEQ_D + h * HEAD;
    const __half* Vg = VT + (size_t)bh * HEAD * TKV;

    for (int s = tid; s < 1024; s += 256) {
        int r = s >> 3, c8 = (s & 7) * 8;
        const float* p = Qg + (size_t)r * SEQ_D + c8;
        float4 v0 = *(const float4*)p, v1 = *(const float4*)(p + 4);
        uint4 u = { pack2(v0.x, v0.y), pack2(v0.z, v0.w),
                    pack2(v1.x, v1.y), pack2(v1.z, v1.w) };
        *(uint4*)&Qs[r * 72 + c8] = u;
    }
    for (int s = tid; s < 2048; s += 256) {
        int r = s >> 3, c8 = (s & 7) * 8;
        *(uint4*)&Ks[r * 72 + c8] = *(const uint4*)(Kg + (size_t)r * SEQ_D + c8);
    }
    for (int s = tid; s < 2048; s += 256) {
        int r = s >> 5, c8 = (s & 31) * 8;
        *(uint4*)&Vs[r * 264 + c8] = *(const uint4*)(Vg + (size_t)r * TKV + c8);
    }
    __syncthreads();

    const int lr = lane & 15;
    const int lc = lane >> 4;
    const int g4 = lane >> 2;
    const int t4 = lane & 3;

    float acc[32][4];
#pragma unroll
    for (int nt = 0; nt < 32; nt++)
#pragma unroll
        for (int j = 0; j < 4; j++) acc[nt][j] = 0.0f;

#pragma unroll
    for (int ks = 0; ks < 4; ks++) {
        uint32_t af[4];
        LDMX4(af[0], af[1], af[2], af[3],
              sptr(&Qs[(warp * 16 + lr) * 72 + ks * 16 + lc * 8]));
#pragma unroll
        for (int np = 0; np < 16; np++) {
            uint32_t r0, r1, r2, r3;
            LDMX4(r0, r1, r2, r3,
                  sptr(&Ks[(np * 16 + lr) * 72 + ks * 16 + lc * 8]));
            uint32_t b0[2] = { r0, r2 };
            uint32_t b1[2] = { r1, r3 };
            MMA16816(acc[np * 2 + 0], af, b0);
            MMA16816(acc[np * 2 + 1], af, b1);
        }
    }

    float mx0 = -1e30f, mx1 = -1e30f;
#pragma unroll
    for (int nt = 0; nt < 32; nt++) {
#pragma unroll
        for (int j = 0; j < 4; j++) acc[nt][j] *= 0.125f;
        mx0 = fmaxf(mx0, fmaxf(acc[nt][0], acc[nt][1]));
        mx1 = fmaxf(mx1, fmaxf(acc[nt][2], acc[nt][3]));
    }
    mx0 = fmaxf(mx0, __shfl_xor_sync(0xffffffffu, mx0, 1));
    mx0 = fmaxf(mx0, __shfl_xor_sync(0xffffffffu, mx0, 2));
    mx1 = fmaxf(mx1, __shfl_xor_sync(0xffffffffu, mx1, 1));
    mx1 = fmaxf(mx1, __shfl_xor_sync(0xffffffffu, mx1, 2));

    float s0 = 0.0f, s1 = 0.0f;
#pragma unroll
    for (int nt = 0; nt < 32; nt++) {
        acc[nt][0] = __expf(acc[nt][0] - mx0);
        acc[nt][1] = __expf(acc[nt][1] - mx0);
        acc[nt][2] = __expf(acc[nt][2] - mx1);
        acc[nt][3] = __expf(acc[nt][3] - mx1);
        s0 += acc[nt][0] + acc[nt][1];
        s1 += acc[nt][2] + acc[nt][3];
    }
    s0 += __shfl_xor_sync(0xffffffffu, s0, 1);
    s0 += __shfl_xor_sync(0xffffffffu, s0, 2);
    s1 += __shfl_xor_sync(0xffffffffu, s1, 1);
    s1 += __shfl_xor_sync(0xffffffffu, s1, 2);
    const float inv0 = 1.0f / s0;
    const float inv1 = 1.0f / s1;

    float oacc[8][4];
#pragma unroll
    for (int nt = 0; nt < 8; nt++)
#pragma unroll
        for (int j = 0; j < 4; j++) oacc[nt][j] = 0.0f;

#pragma unroll
    for (int kc = 0; kc < 16; kc++) {
        uint32_t af[4];
        af[0] = pack2(acc[2 * kc][0],     acc[2 * kc][1]);
        af[1] = pack2(acc[2 * kc][2],     acc[2 * kc][3]);
        af[2] = pack2(acc[2 * kc + 1][0], acc[2 * kc + 1][1]);
        af[3] = pack2(acc[2 * kc + 1][2], acc[2 * kc + 1][3]);
#pragma unroll
        for (int np = 0; np < 4; np++) {
            uint32_t r0, r1, r2, r3;
            LDMX4(r0, r1, r2, r3,
                  sptr(&Vs[(np * 16 + lr) * 264 + kc * 16 + lc * 8]));
            uint32_t b0[2] = { r0, r2 };
            uint32_t b1[2] = { r1, r3 };
            MMA16816(oacc[np * 2 + 0], af, b0);
            MMA16816(oacc[np * 2 + 1], af, b1);
        }
    }

    __half* Og = attn + ((size_t)b * LQ + q0 + warp * 16) * SEQ_D + h * HEAD;
#pragma unroll
    for (int nt = 0; nt < 8; nt++) {
        int c = nt * 8 + 2 * t4;
        float2 v0 = make_float2(oacc[nt][0] * inv0, oacc[nt][1] * inv0);
        float2 v1 = make_float2(oacc[nt][2] * inv1, oacc[nt][3] * inv1);
        *(__half2*)(Og + (size_t)g4 * SEQ_D + c)       = __float22half2_rn(v0);
        *(__half2*)(Og + (size_t)(g4 + 8) * SEQ_D + c) = __float22half2_rn(v1);
    }
}

// ---------------- fp32 -> fp16 elementwise ----------------
__global__ __launch_bounds__(256)
void f2h_kernel(const float* __restrict__ X, __half* __restrict__ Y)
{
    size_t s = (size_t)blockIdx.x * 256 + threadIdx.x;
    const float* p = X + s * 8;
    float4 v0 = *(const float4*)p, v1 = *(const float4*)(p + 4);
    uint4 u = { pack2(v0.x, v0.y), pack2(v0.z, v0.w),
                pack2(v1.x, v1.y), pack2(v1.z, v1.w) };
    *(uint4*)(Y + s * 8) = u;
}

// ---------------- weight transpose ----------------
__global__ __launch_bounds__(256)
void transpose_kernel(const float* __restrict__ W, __half* __restrict__ WT,
                      int K, int N)
{
    __shared__ float t[32][33];
    int n0 = blockIdx.x * 32, k0 = blockIdx.y * 32;
    int tx = threadIdx.x & 31, ty = threadIdx.x >> 5;
#pragma unroll
    for (int i = 0; i < 32; i += 8)
        t[ty + i][tx] = W[(size_t)(k0 + ty + i) * N + n0 + tx];
    __syncthreads();
#pragma unroll
    for (int i = 0; i < 32; i += 8)
        WT[(size_t)(n0 + ty + i) * K + k0 + tx] = __float2half_rn(t[tx][ty + i]);
}

// ---------------- V transpose per head ----------------
__global__ __launch_bounds__(256)
void vt_kernel(const float* __restrict__ V, __half* __restrict__ VT)
{
    __shared__ float t[32][33];
    int t0 = blockIdx.x * 32;
    int d0 = blockIdx.y * 32;
    int bh = blockIdx.z;
    int b = bh / NH, h = bh % NH;
    int tx = threadIdx.x & 31, ty = threadIdx.x >> 5;
#pragma unroll
    for (int i = 0; i < 32; i += 8)
        t[ty + i][tx] = V[((size_t)b * TKV + t0 + ty + i) * SEQ_D + h * HEAD + d0 + tx];
    __syncthreads();
#pragma unroll
    for (int i = 0; i < 32; i += 8)
        VT[((size_t)bh * HEAD + d0 + ty + i) * TKV + t0 + tx] =
            __float2half_rn(t[tx][ty + i]);
}

// ---------------- LayerNorm ----------------
template <typename TOUT>
__global__ __launch_bounds__(256)
void ln_kernel(const float* __restrict__ X, const float* __restrict__ g,
               const float* __restrict__ b, TOUT* __restrict__ Y, int D)
{
    long row = blockIdx.x;
    const float4* x4 = (const float4*)(X + row * (long)D);
    const float4* g4 = (const float4*)g;
    const float4* b4 = (const float4*)b;
    int n4 = D >> 2;

    float s = 0.0f, s2 = 0.0f;
    for (int i = threadIdx.x; i < n4; i += 256) {
        float4 v = x4[i];
        s  += v.x + v.y + v.z + v.w;
        s2 += v.x * v.x + v.y * v.y + v.z * v.z + v.w * v.w;
    }
#pragma unroll
    for (int o = 16; o; o >>= 1) {
        s  += __shfl_xor_sync(0xffffffffu, s, o);
        s2 += __shfl_xor_sync(0xffffffffu, s2, o);
    }
    __shared__ float sh[16];
    int w = threadIdx.x >> 5, lane = threadIdx.x & 31;
    if (lane == 0) { sh[w] = s; sh[w + 8] = s2; }
    __syncthreads();
    if (threadIdx.x < 32) {
        float a = (threadIdx.x < 8) ? sh[threadIdx.x] : 0.0f;
        float c = (threadIdx.x < 8) ? sh[threadIdx.x + 8] : 0.0f;
#pragma unroll
        for (int o = 16; o; o >>= 1) {
            a += __shfl_xor_sync(0xffffffffu, a, o);
            c += __shfl_xor_sync(0xffffffffu, c, o);
        }
        if (threadIdx.x == 0) { sh[0] = a; sh[1] = c; }
    }
    __syncthreads();
    float invD = 1.0f / (float)D;
    float mu   = sh[0] * invD;
    float var  = sh[1] * invD - mu * mu;
    float rstd = rsqrtf(var + EPSF);

    for (int i = threadIdx.x; i < n4; i += 256) {
        float4 v = x4[i], gg = g4[i], bb = b4[i];
        v.x = (v.x - mu) * rstd * gg.x + bb.x;
        v.y = (v.y - mu) * rstd * gg.y + bb.y;
        v.z = (v.z - mu) * rstd * gg.z + bb.z;
        v.w = (v.w - mu) * rstd * gg.w + bb.w;
        if (sizeof(TOUT) == 4) {
            ((float4*)(void*)(Y + row * (long)D))[i] = v;
        } else {
            uint2 u = { pack2(v.x, v.y), pack2(v.z, v.w) };
            ((uint2*)(void*)(Y + row * (long)D))[i] = u;
        }
    }
}

// ---------------- launch ----------------
extern "C" void kernel_launch(void* const* d_in, const int* in_sizes, int n_in,
                              void* d_out, int out_size)
{
    const float* grid      = (const float*)d_in[0];
    const float* query_pos = (const float*)d_in[1];
    const float* Wq        = (const float*)d_in[2];
    const float* Wk        = (const float*)d_in[3];
    const float* Wv        = (const float*)d_in[4];
    const float* Wo        = (const float*)d_in[5];
    const float* lng_g     = (const float*)d_in[6];
    const float* lng_b     = (const float*)d_in[7];
    const float* lnq_g     = (const float*)d_in[8];
    const float* lnq_b     = (const float*)d_in[9];
    const float* lnm_g     = (const float*)d_in[10];
    const float* lnm_b     = (const float*)d_in[11];
    const float* W1        = (const float*)d_in[12];
    const float* b1        = (const float*)d_in[13];
    const float* W2        = (const float*)d_in[14];
    const float* b2        = (const float*)d_in[15];
    float* out = (float*)d_out;

    float *Kp, *V, *Q, *x;
    __half *gridh, *Kn, *qn, *attn, *xn, *hb;
    __half *WkT, *WvT, *WqT, *WoT, *W1T, *W2T, *VT;
    cudaGetSymbolAddress((void**)&gridh, g_gridh);
    cudaGetSymbolAddress((void**)&Kp,   g_Kpre);
    cudaGetSymbolAddress((void**)&Kn,   g_Kn);
    cudaGetSymbolAddress((void**)&V,    g_V);
    cudaGetSymbolAddress((void**)&qn,   g_qn);
    cudaGetSymbolAddress((void**)&Q,    g_Q);
    cudaGetSymbolAddress((void**)&attn, g_attn);
    cudaGetSymbolAddress((void**)&x,    g_x);
    cudaGetSymbolAddress((void**)&xn,   g_xn);
    cudaGetSymbolAddress((void**)&hb,   g_h);
    cudaGetSymbolAddress((void**)&WkT,  g_WkT);
    cudaGetSymbolAddress((void**)&WvT,  g_WvT);
    cudaGetSymbolAddress((void**)&WqT,  g_WqT);
    cudaGetSymbolAddress((void**)&WoT,  g_WoT);
    cudaGetSymbolAddress((void**)&W1T,  g_W1T);
    cudaGetSymbolAddress((void**)&W2T,  g_W2T);
    cudaGetSymbolAddress((void**)&VT,   g_VT);

    cudaFuncSetAttribute(fused_attn,
        cudaFuncAttributeMaxDynamicSharedMemorySize, FA_SMEM);
    cudaFuncSetAttribute(gemm_h<float, EPI_NONE>,
        cudaFuncAttributeMaxDynamicSharedMemorySize, GH_SMEM);
    cudaFuncSetAttribute(gemm_h<float, EPI_RESID>,
        cudaFuncAttributeMaxDynamicSharedMemorySize, GH_SMEM);
    cudaFuncSetAttribute(gemm_h<__half, EPI_GELU_BIAS>,
        cudaFuncAttributeMaxDynamicSharedMemorySize, GH_SMEM);
    cudaFuncSetAttribute(gemm_h<float, EPI_BIAS_RESID>,
        cudaFuncAttributeMaxDynamicSharedMemorySize, GH_SMEM);

    dim3 blk(256);
    const int MG = BB * TKV;       // 4096
    const int MQ = BB * LQ;        // 16384
    const int HD = MULT * SEQ_D;   // 4096

    // 0) fp16 conversions / transposes
    f2h_kernel<<<(MG * GRID_D) / (256 * 8), blk>>>(grid, gridh);
    transpose_kernel<<<dim3(SEQ_D / 32, GRID_D / 32), blk>>>(Wk, WkT, GRID_D, SEQ_D);
    transpose_kernel<<<dim3(SEQ_D / 32, GRID_D / 32), blk>>>(Wv, WvT, GRID_D, SEQ_D);
    transpose_kernel<<<dim3(SEQ_D / 32, POS_D / 32),  blk>>>(Wq, WqT, POS_D, SEQ_D);
    transpose_kernel<<<dim3(SEQ_D / 32, SEQ_D / 32),  blk>>>(Wo, WoT, SEQ_D, SEQ_D);
    transpose_kernel<<<dim3(HD / 32, SEQ_D / 32),     blk>>>(W1, W1T, SEQ_D, HD);
    transpose_kernel<<<dim3(SEQ_D / 32, HD / 32),     blk>>>(W2, W2T, HD, SEQ_D);

    // 1) Kpre = grid @ Wk ; V = grid @ Wv
    gemm_h<float, EPI_NONE><<<dim3(SEQ_D / GH_BN, MG / GH_BM), blk, GH_SMEM>>>(
        gridh, WkT, nullptr, nullptr, Kp, MG, SEQ_D, GRID_D,
        GRID_D, GRID_D, SEQ_D, 1.0f);
    gemm_h<float, EPI_NONE><<<dim3(SEQ_D / GH_BN, MG / GH_BM), blk, GH_SMEM>>>(
        gridh, WvT, nullptr, nullptr, V, MG, SEQ_D, GRID_D,
        GRID_D, GRID_D, SEQ_D, 1.0f);

    // 1b) VT
    vt_kernel<<<dim3(TKV / 32, HEAD / 32, BB * NH), blk>>>(V, VT);

    // 2) LNs -> fp16
    ln_kernel<__half><<<MG, 256>>>(Kp, lng_g, lng_b, Kn, SEQ_D);
    ln_kernel<__half><<<MQ, 256>>>(query_pos, lnq_g, lnq_b, qn, POS_D);

    // 3) Q = qn @ Wq
    gemm_h<float, EPI_NONE><<<dim3(SEQ_D / GH_BN, MQ / GH_BM), blk, GH_SMEM>>>(
        qn, WqT, nullptr, nullptr, Q, MQ, SEQ_D, POS_D,
        POS_D, POS_D, SEQ_D, 1.0f);

    // 4-6) fused attention -> attn fp16
    fused_attn<<<dim3(LQ / 128, BB * NH), blk, FA_SMEM>>>(Q, Kn, VT, attn);

    // 7) x = Q + attn @ Wo
    gemm_h<float, EPI_RESID><<<dim3(SEQ_D / GH_BN, MQ / GH_BM), blk, GH_SMEM>>>(
        attn, WoT, nullptr, Q, x, MQ, SEQ_D, SEQ_D,
        SEQ_D, SEQ_D, SEQ_D, 1.0f);

    // 8) xn = LN(x) -> fp16
    ln_kernel<__half><<<MQ, 256>>>(x, lnm_g, lnm_b, xn, SEQ_D);

    // 9) hb = gelu(xn @ W1 + b1) -> fp16
    gemm_h<__half, EPI_GELU_BIAS><<<dim3(HD / GH_BN, MQ / GH_BM), blk, GH_SMEM>>>(
        xn, W1T, b1, nullptr, hb, MQ, HD, SEQ_D,
        SEQ_D, SEQ_D, HD, 1.0f);

    // 10) out = x + hb @ W2 + b2
    gemm_h<float, EPI_BIAS_RESID><<<dim3(SEQ_D / GH_BN, MQ / GH_BM), blk, GH_SMEM>>>(
        hb, W2T, b2, x, out, MQ, SEQ_D, HD,
        HD, HD, SEQ_D, 1.0f);
}

// round 14
// speedup vs baseline: 1.1412x; 1.1412x over previous
#include <cuda_runtime.h>
#include <cuda_fp16.h>
#include <math.h>
#include <stdint.h>

// Problem constants
#define BB      16
#define GRID_D  1024
#define SEQ_D   1024
#define POS_D   512
#define NH      16
#define HEAD    64
#define LQ      1024
#define TKV     256
#define MULT    4
#define EPSF    1e-5f

// ---------------- scratch (static device memory) ---------------
__device__ __half g_gridh[(size_t)BB * TKV * GRID_D];
__device__ float  g_KV  [(size_t)BB * TKV * 2 * SEQ_D];       // [4096][2048]: Kpre | V
__device__ __half g_Kn  [(size_t)BB * TKV * SEQ_D];
__device__ __half g_qn  [(size_t)BB * LQ * POS_D];
__device__ __half g_Qh  [(size_t)BB * LQ * SEQ_D];            // fp16 Q
__device__ __half g_attn[(size_t)BB * LQ * SEQ_D];
__device__ float  g_x   [(size_t)BB * LQ * SEQ_D];
__device__ __half g_xn  [(size_t)BB * LQ * SEQ_D];
__device__ __half g_h   [(size_t)BB * LQ * MULT * SEQ_D];
__device__ __half g_WkvT[(size_t)2 * SEQ_D * GRID_D];         // [2048][1024]: WkT | WvT
__device__ __half g_WqT [(size_t)SEQ_D * POS_D];
__device__ __half g_WoT [(size_t)SEQ_D * SEQ_D];
__device__ __half g_W1T [(size_t)MULT * SEQ_D * SEQ_D];
__device__ __half g_W2T [(size_t)SEQ_D * MULT * SEQ_D];
__device__ __half g_VT  [(size_t)BB * NH * HEAD * TKV];

// ---------------- helpers ----------------
__device__ __forceinline__ float gelu_f(float v) {
    float v3 = v * v * v;
    return 0.5f * v * (1.0f + tanhf(0.7978845608028654f * (v + 0.044715f * v3)));
}
__device__ __forceinline__ uint32_t sptr(const void* p) {
    uint32_t a;
    asm("{ .reg .u64 t; cvta.to.shared.u64 t, %1; cvt.u32.u64 %0, t; }" : "=r"(a) : "l"(p));
    return a;
}
__device__ __forceinline__ uint32_t pack2(float a, float b) {
    __half2 h = __float22half2_rn(make_float2(a, b));
    return *reinterpret_cast<uint32_t*>(&h);
}

#define CP_ASYNC16(dst, src) \
    asm volatile("cp.async.cg.shared.global [%0], [%1], 16;" \
                 :: "r"(dst), "l"(src) : "memory")
#define CP_COMMIT() asm volatile("cp.async.commit_group;" ::: "memory")
#define CP_WAIT0()  asm volatile("cp.async.wait_group 0;" ::: "memory")

#define LDMX4(r0, r1, r2, r3, addr) \
    asm volatile("ldmatrix.sync.aligned.m8n8.x4.shared.b16 {%0,%1,%2,%3}, [%4];" \
                 : "=r"(r0), "=r"(r1), "=r"(r2), "=r"(r3) : "r"(addr))

#define MMA16816(d, a, b) \
    asm volatile("mma.sync.aligned.m16n8k16.row.col.f32.f16.f16.f32 " \
                 "{%0,%1,%2,%3}, {%4,%5,%6,%7}, {%8,%9}, {%0,%1,%2,%3};" \
                 : "+f"((d)[0]), "+f"((d)[1]), "+f"((d)[2]), "+f"((d)[3]) \
                 : "r"((a)[0]), "r"((a)[1]), "r"((a)[2]), "r"((a)[3]), \
                   "r"((b)[0]), "r"((b)[1]))

enum { EPI_NONE = 0, EPI_RESID = 1, EPI_GELU_BIAS = 2, EPI_BIAS_RESID = 3 };

// =================================================================
// fp16 tensor-core GEMM (NT): C[M,N] = alpha * A[M,K] @ BT[N,K]^T (+epi)
// Round-9-proven config: BM=128, BN=128, BK=32; 8 warps of 32x64;
// 2-stage cp.async; static SMEM 40KB; 2 CTAs/SM.
// TR = residual element type (float or __half).
// =================================================================
template <typename TC, typename TR, int EPI>
__global__ __launch_bounds__(256, 2)
void gemm_h(const __half* __restrict__ A, const __half* __restrict__ BT,
            const float* __restrict__ bias, const TR* __restrict__ res,
            TC* __restrict__ C,
            int M, int N, int K, int lda, int ldb, int ldc, float alpha)
{
    constexpr int BM = 128, BN = 128, BK = 32;
    constexpr int STR = 40;

    __shared__ __half As[2][BM][STR];
    __shared__ __half Bs[2][BN][STR];

    const int tid  = threadIdx.x;
    const int lane = tid & 31;
    const int warp = tid >> 5;
    const int wm   = warp >> 1;
    const int wn   = warp & 1;
    const int m0   = blockIdx.y * BM;
    const int n0   = blockIdx.x * BN;

    float acc[2][8][4];
#pragma unroll
    for (int mt = 0; mt < 2; mt++)
#pragma unroll
        for (int nt = 0; nt < 8; nt++)
#pragma unroll
            for (int j = 0; j < 4; j++) acc[mt][nt][j] = 0.0f;

    auto issue = [&](int buf, int k0) {
#pragma unroll
        for (int i = 0; i < 2; i++) {
            int s = tid + i * 256, r = s >> 2, cs = s & 3;
            CP_ASYNC16(sptr(&As[buf][r][cs * 8]),
                       A + (size_t)(m0 + r) * lda + k0 + cs * 8);
        }
#pragma unroll
        for (int i = 0; i < 2; i++) {
            int s = tid + i * 256, r = s >> 2, cs = s & 3;
            CP_ASYNC16(sptr(&Bs[buf][r][cs * 8]),
                       BT + (size_t)(n0 + r) * ldb + k0 + cs * 8);
        }
        CP_COMMIT();
    };

    const int lr = lane & 15;
    const int lc = lane >> 4;

    auto compute = [&](int buf) {
#pragma unroll
        for (int ks = 0; ks < 2; ks++) {
            uint32_t af[2][4];
#pragma unroll
            for (int mt = 0; mt < 2; mt++) {
                uint32_t ad = sptr(&As[buf][wm * 32 + mt * 16 + lr][ks * 16 + lc * 8]);
                LDMX4(af[mt][0], af[mt][1], af[mt][2], af[mt][3], ad);
            }
            uint32_t bf[8][2];
#pragma unroll
            for (int np = 0; np < 4; np++) {
                uint32_t r0, r1, r2, r3;
                uint32_t bd = sptr(&Bs[buf][wn * 64 + np * 16 + lr][ks * 16 + lc * 8]);
                LDMX4(r0, r1, r2, r3, bd);
                bf[np * 2 + 0][0] = r0; bf[np * 2 + 0][1] = r2;
                bf[np * 2 + 1][0] = r1; bf[np * 2 + 1][1] = r3;
            }
#pragma unroll
            for (int mt = 0; mt < 2; mt++)
#pragma unroll
                for (int nt = 0; nt < 8; nt++)
                    MMA16816(acc[mt][nt], af[mt], bf[nt]);
        }
    };

    const int nk = K / BK;
    issue(0, 0);
    for (int it = 0; it < nk; ++it) {
        const int cur = it & 1;
        CP_WAIT0();
        __syncthreads();
        if (it + 1 < nk) issue(cur ^ 1, (it + 1) * BK);
        compute(cur);
    }

    const int g4 = lane >> 2, t4 = lane & 3;
#pragma unroll
    for (int mt = 0; mt < 2; mt++) {
#pragma unroll
        for (int nt = 0; nt < 8; nt++) {
            int r = m0 + wm * 32 + mt * 16 + g4;
            int c = n0 + wn * 64 + nt * 8 + 2 * t4;
#pragma unroll
            for (int half = 0; half < 2; half++) {
                int rr = r + half * 8;
                float2 v = make_float2(acc[mt][nt][half * 2 + 0] * alpha,
                                       acc[mt][nt][half * 2 + 1] * alpha);
                if (EPI == EPI_GELU_BIAS) {
                    float2 bv = *(const float2*)(bias + c);
                    v.x = gelu_f(v.x + bv.x);
                    v.y = gelu_f(v.y + bv.y);
                } else if (EPI == EPI_RESID || EPI == EPI_BIAS_RESID) {
                    float2 rv;
                    if (sizeof(TR) == 2) {
                        __half2 hh = *(const __half2*)((const __half*)(const void*)res
                                        + (size_t)rr * ldc + c);
                        rv = __half22float2(hh);
                    } else {
                        rv = *(const float2*)((const float*)(const void*)res
                                        + (size_t)rr * ldc + c);
                    }
                    if (EPI == EPI_BIAS_RESID) {
                        float2 bv = *(const float2*)(bias + c);
                        rv.x += bv.x; rv.y += bv.y;
                    }
                    v.x += rv.x; v.y += rv.y;
                }
                if (sizeof(TC) == 4) {
                    *(float2*)((float*)(void*)C + (size_t)rr * ldc + c) = v;
                } else {
                    __half2 h = __float22half2_rn(v);
                    *(__half2*)((__half*)(void*)C + (size_t)rr * ldc + c) = h;
                }
            }
        }
    }
}

// =================================================================
// Fused attention (round-9-proven; Q now fp16)
// =================================================================
#define FA_QS_OFF 0
#define FA_KS_OFF (128 * 72)
#define FA_VS_OFF (128 * 72 + 256 * 72)
#define FA_SMEM   ((128 * 72 + 256 * 72 + 64 * 264) * 2)

__global__ __launch_bounds__(256, 1)
void fused_attn(const __half* __restrict__ Q, const __half* __restrict__ Kn,
                const __half* __restrict__ VT, __half* __restrict__ attn)
{
    extern __shared__ __half fsm[];
    __half* Qs = fsm + FA_QS_OFF;
    __half* Ks = fsm + FA_KS_OFF;
    __half* Vs = fsm + FA_VS_OFF;

    const int tid  = threadIdx.x;
    const int lane = tid & 31;
    const int warp = tid >> 5;
    const int q0   = blockIdx.x * 128;
    const int bh   = blockIdx.y;
    const int b    = bh >> 4;
    const int h    = bh & 15;

    const __half* Qg = Q  + ((size_t)b * LQ + q0) * SEQ_D + h * HEAD;
    const __half* Kg = Kn + (size_t)b * TKV * SEQ_D + h * HEAD;
    const __half* Vg = VT + (size_t)bh * HEAD * TKV;

    for (int s = tid; s < 1024; s += 256) {
        int r = s >> 3, c8 = (s & 7) * 8;
        *(uint4*)&Qs[r * 72 + c8] = *(const uint4*)(Qg + (size_t)r * SEQ_D + c8);
    }
    for (int s = tid; s < 2048; s += 256) {
        int r = s >> 3, c8 = (s & 7) * 8;
        *(uint4*)&Ks[r * 72 + c8] = *(const uint4*)(Kg + (size_t)r * SEQ_D + c8);
    }
    for (int s = tid; s < 2048; s += 256) {
        int r = s >> 5, c8 = (s & 31) * 8;
        *(uint4*)&Vs[r * 264 + c8] = *(const uint4*)(Vg + (size_t)r * TKV + c8);
    }
    __syncthreads();

    const int lr = lane & 15;
    const int lc = lane >> 4;
    const int g4 = lane >> 2;
    const int t4 = lane & 3;

    float acc[32][4];
#pragma unroll
    for (int nt = 0; nt < 32; nt++)
#pragma unroll
        for (int j = 0; j < 4; j++) acc[nt][j] = 0.0f;

#pragma unroll
    for (int ks = 0; ks < 4; ks++) {
        uint32_t af[4];
        LDMX4(af[0], af[1], af[2], af[3],
              sptr(&Qs[(warp * 16 + lr) * 72 + ks * 16 + lc * 8]));
#pragma unroll
        for (int np = 0; np < 16; np++) {
            uint32_t r0, r1, r2, r3;
            LDMX4(r0, r1, r2, r3,
                  sptr(&Ks[(np * 16 + lr) * 72 + ks * 16 + lc * 8]));
            uint32_t b0[2] = { r0, r2 };
            uint32_t b1[2] = { r1, r3 };
            MMA16816(acc[np * 2 + 0], af, b0);
            MMA16816(acc[np * 2 + 1], af, b1);
        }
    }

    float mx0 = -1e30f, mx1 = -1e30f;
#pragma unroll
    for (int nt = 0; nt < 32; nt++) {
#pragma unroll
        for (int j = 0; j < 4; j++) acc[nt][j] *= 0.125f;
        mx0 = fmaxf(mx0, fmaxf(acc[nt][0], acc[nt][1]));
        mx1 = fmaxf(mx1, fmaxf(acc[nt][2], acc[nt][3]));
    }
    mx0 = fmaxf(mx0, __shfl_xor_sync(0xffffffffu, mx0, 1));
    mx0 = fmaxf(mx0, __shfl_xor_sync(0xffffffffu, mx0, 2));
    mx1 = fmaxf(mx1, __shfl_xor_sync(0xffffffffu, mx1, 1));
    mx1 = fmaxf(mx1, __shfl_xor_sync(0xffffffffu, mx1, 2));

    float s0 = 0.0f, s1 = 0.0f;
#pragma unroll
    for (int nt = 0; nt < 32; nt++) {
        acc[nt][0] = __expf(acc[nt][0] - mx0);
        acc[nt][1] = __expf(acc[nt][1] - mx0);
        acc[nt][2] = __expf(acc[nt][2] - mx1);
        acc[nt][3] = __expf(acc[nt][3] - mx1);
        s0 += acc[nt][0] + acc[nt][1];
        s1 += acc[nt][2] + acc[nt][3];
    }
    s0 += __shfl_xor_sync(0xffffffffu, s0, 1);
    s0 += __shfl_xor_sync(0xffffffffu, s0, 2);
    s1 += __shfl_xor_sync(0xffffffffu, s1, 1);
    s1 += __shfl_xor_sync(0xffffffffu, s1, 2);
    const float inv0 = 1.0f / s0;
    const float inv1 = 1.0f / s1;

    float oacc[8][4];
#pragma unroll
    for (int nt = 0; nt < 8; nt++)
#pragma unroll
        for (int j = 0; j < 4; j++) oacc[nt][j] = 0.0f;

#pragma unroll
    for (int kc = 0; kc < 16; kc++) {
        uint32_t af[4];
        af[0] = pack2(acc[2 * kc][0],     acc[2 * kc][1]);
        af[1] = pack2(acc[2 * kc][2],     acc[2 * kc][3]);
        af[2] = pack2(acc[2 * kc + 1][0], acc[2 * kc + 1][1]);
        af[3] = pack2(acc[2 * kc + 1][2], acc[2 * kc + 1][3]);
#pragma unroll
        for (int np = 0; np < 4; np++) {
            uint32_t r0, r1, r2, r3;
            LDMX4(r0, r1, r2, r3,
                  sptr(&Vs[(np * 16 + lr) * 264 + kc * 16 + lc * 8]));
            uint32_t b0[2] = { r0, r2 };
            uint32_t b1[2] = { r1, r3 };
            MMA16816(oacc[np * 2 + 0], af, b0);
            MMA16816(oacc[np * 2 + 1], af, b1);
        }
    }

    __half* Og = attn + ((size_t)b * LQ + q0 + warp * 16) * SEQ_D + h * HEAD;
#pragma unroll
    for (int nt = 0; nt < 8; nt++) {
        int c = nt * 8 + 2 * t4;
        float2 v0 = make_float2(oacc[nt][0] * inv0, oacc[nt][1] * inv0);
        float2 v1 = make_float2(oacc[nt][2] * inv1, oacc[nt][3] * inv1);
        *(__half2*)(Og + (size_t)g4 * SEQ_D + c)       = __float22half2_rn(v0);
        *(__half2*)(Og + (size_t)(g4 + 8) * SEQ_D + c) = __float22half2_rn(v1);
    }
}

// ---------------- fp32 -> fp16 elementwise ----------------
__global__ __launch_bounds__(256)
void f2h_kernel(const float* __restrict__ X, __half* __restrict__ Y)
{
    size_t s = (size_t)blockIdx.x * 256 + threadIdx.x;
    const float* p = X + s * 8;
    float4 v0 = *(const float4*)p, v1 = *(const float4*)(p + 4);
    uint4 u = { pack2(v0.x, v0.y), pack2(v0.z, v0.w),
                pack2(v1.x, v1.y), pack2(v1.z, v1.w) };
    *(uint4*)(Y + s * 8) = u;
}

// ---------------- weight transpose ----------------
__global__ __launch_bounds__(256)
void transpose_kernel(const float* __restrict__ W, __half* __restrict__ WT,
                      int K, int N)
{
    __shared__ float t[32][33];
    int n0 = blockIdx.x * 32, k0 = blockIdx.y * 32;
    int tx = threadIdx.x & 31, ty = threadIdx.x >> 5;
#pragma unroll
    for (int i = 0; i < 32; i += 8)
        t[ty + i][tx] = W[(size_t)(k0 + ty + i) * N + n0 + tx];
    __syncthreads();
#pragma unroll
    for (int i = 0; i < 32; i += 8)
        WT[(size_t)(n0 + ty + i) * K + k0 + tx] = __float2half_rn(t[tx][ty + i]);
}

// ---------------- V transpose per head (reads V half of KV) ----------------
__global__ __launch_bounds__(256)
void vt_kernel(const float* __restrict__ KV, __half* __restrict__ VT)
{
    __shared__ float t[32][33];
    int t0 = blockIdx.x * 32;
    int d0 = blockIdx.y * 32;
    int bh = blockIdx.z;
    int b = bh / NH, h = bh % NH;
    int tx = threadIdx.x & 31, ty = threadIdx.x >> 5;
#pragma unroll
    for (int i = 0; i < 32; i += 8)
        t[ty + i][tx] = KV[((size_t)b * TKV + t0 + ty + i) * (2 * SEQ_D)
                           + SEQ_D + h * HEAD + d0 + tx];
    __syncthreads();
#pragma unroll
    for (int i = 0; i < 32; i += 8)
        VT[((size_t)bh * HEAD + d0 + ty + i) * TKV + t0 + tx] =
            __float2half_rn(t[tx][ty + i]);
}

// ---------------- LayerNorm (ldx = input row stride) ----------------
template <typename TOUT>
__global__ __launch_bounds__(256)
void ln_kernel(const float* __restrict__ X, const float* __restrict__ g,
               const float* __restrict__ b, TOUT* __restrict__ Y, int D, int ldx)
{
    long row = blockIdx.x;
    const float4* x4 = (const float4*)(X + row * (long)ldx);
    const float4* g4 = (const float4*)g;
    const float4* b4 = (const float4*)b;
    int n4 = D >> 2;

    float s = 0.0f, s2 = 0.0f;
    for (int i = threadIdx.x; i < n4; i += 256) {
        float4 v = x4[i];
        s  += v.x + v.y + v.z + v.w;
        s2 += v.x * v.x + v.y * v.y + v.z * v.z + v.w * v.w;
    }
#pragma unroll
    for (int o = 16; o; o >>= 1) {
        s  += __shfl_xor_sync(0xffffffffu, s, o);
        s2 += __shfl_xor_sync(0xffffffffu, s2, o);
    }
    __shared__ float sh[16];
    int w = threadIdx.x >> 5, lane = threadIdx.x & 31;
    if (lane == 0) { sh[w] = s; sh[w + 8] = s2; }
    __syncthreads();
    if (threadIdx.x < 32) {
        float a = (threadIdx.x < 8) ? sh[threadIdx.x] : 0.0f;
        float c = (threadIdx.x < 8) ? sh[threadIdx.x + 8] : 0.0f;
#pragma unroll
        for (int o = 16; o; o >>= 1) {
            a += __shfl_xor_sync(0xffffffffu, a, o);
            c += __shfl_xor_sync(0xffffffffu, c, o);
        }
        if (threadIdx.x == 0) { sh[0] = a; sh[1] = c; }
    }
    __syncthreads();
    float invD = 1.0f / (float)D;
    float mu   = sh[0] * invD;
    float var  = sh[1] * invD - mu * mu;
    float rstd = rsqrtf(var + EPSF);

    for (int i = threadIdx.x; i < n4; i += 256) {
        float4 v = x4[i], gg = g4[i], bb = b4[i];
        v.x = (v.x - mu) * rstd * gg.x + bb.x;
        v.y = (v.y - mu) * rstd * gg.y + bb.y;
        v.z = (v.z - mu) * rstd * gg.z + bb.z;
        v.w = (v.w - mu) * rstd * gg.w + bb.w;
        if (sizeof(TOUT) == 4) {
            ((float4*)(void*)(Y + row * (long)D))[i] = v;
        } else {
            uint2 u = { pack2(v.x, v.y), pack2(v.z, v.w) };
            ((uint2*)(void*)(Y + row * (long)D))[i] = u;
        }
    }
}

// ---------------- launch ----------------
extern "C" void kernel_launch(void* const* d_in, const int* in_sizes, int n_in,
                              void* d_out, int out_size)
{
    const float* grid      = (const float*)d_in[0];
    const float* query_pos = (const float*)d_in[1];
    const float* Wq        = (const float*)d_in[2];
    const float* Wk        = (const float*)d_in[3];
    const float* Wv        = (const float*)d_in[4];
    const float* Wo        = (const float*)d_in[5];
    const float* lng_g     = (const float*)d_in[6];
    const float* lng_b     = (const float*)d_in[7];
    const float* lnq_g     = (const float*)d_in[8];
    const float* lnq_b     = (const float*)d_in[9];
    const float* lnm_g     = (const float*)d_in[10];
    const float* lnm_b     = (const float*)d_in[11];
    const float* W1        = (const float*)d_in[12];
    const float* b1        = (const float*)d_in[13];
    const float* W2        = (const float*)d_in[14];
    const float* b2        = (const float*)d_in[15];
    float* out = (float*)d_out;

    float *KV, *x;
    __half *gridh, *Kn, *qn, *Qh, *attn, *xn, *hb;
    __half *WkvT, *WqT, *WoT, *W1T, *W2T, *VT;
    cudaGetSymbolAddress((void**)&gridh, g_gridh);
    cudaGetSymbolAddress((void**)&KV,   g_KV);
    cudaGetSymbolAddress((void**)&Kn,   g_Kn);
    cudaGetSymbolAddress((void**)&qn,   g_qn);
    cudaGetSymbolAddress((void**)&Qh,   g_Qh);
    cudaGetSymbolAddress((void**)&attn, g_attn);
    cudaGetSymbolAddress((void**)&x,    g_x);
    cudaGetSymbolAddress((void**)&xn,   g_xn);
    cudaGetSymbolAddress((void**)&hb,   g_h);
    cudaGetSymbolAddress((void**)&WkvT, g_WkvT);
    cudaGetSymbolAddress((void**)&WqT,  g_WqT);
    cudaGetSymbolAddress((void**)&WoT,  g_WoT);
    cudaGetSymbolAddress((void**)&W1T,  g_W1T);
    cudaGetSymbolAddress((void**)&W2T,  g_W2T);
    cudaGetSymbolAddress((void**)&VT,   g_VT);

    cudaFuncSetAttribute(fused_attn,
        cudaFuncAttributeMaxDynamicSharedMemorySize, FA_SMEM);

    dim3 blk(256);
    const int MG = BB * TKV;       // 4096
    const int MQ = BB * LQ;        // 16384
    const int HD = MULT * SEQ_D;   // 4096

    // 0) fp16 conversions / transposes
    f2h_kernel<<<(MG * GRID_D) / (256 * 8), blk>>>(grid, gridh);
    transpose_kernel<<<dim3(SEQ_D / 32, GRID_D / 32), blk>>>(Wk, WkvT, GRID_D, SEQ_D);
    transpose_kernel<<<dim3(SEQ_D / 32, GRID_D / 32), blk>>>(
        Wv, WkvT + (size_t)SEQ_D * GRID_D, GRID_D, SEQ_D);
    transpose_kernel<<<dim3(SEQ_D / 32, POS_D / 32),  blk>>>(Wq, WqT, POS_D, SEQ_D);
    transpose_kernel<<<dim3(SEQ_D / 32, SEQ_D / 32),  blk>>>(Wo, WoT, SEQ_D, SEQ_D);
    transpose_kernel<<<dim3(HD / 32, SEQ_D / 32),     blk>>>(W1, W1T, SEQ_D, HD);
    transpose_kernel<<<dim3(SEQ_D / 32, HD / 32),     blk>>>(W2, W2T, HD, SEQ_D);

    // 1) KV = grid @ [Wk | Wv]  (merged, N=2048)
    gemm_h<float, float, EPI_NONE><<<dim3(2 * SEQ_D / 128, MG / 128), blk>>>(
        gridh, WkvT, nullptr, nullptr, KV, MG, 2 * SEQ_D, GRID_D,
        GRID_D, GRID_D, 2 * SEQ_D, 1.0f);

    // 1b) VT from V half of KV
    vt_kernel<<<dim3(TKV / 32, HEAD / 32, BB * NH), blk>>>(KV, VT);

    // 2) Kn = LN(KV[:, :1024]) -> fp16 ; qn = LN(query_pos) -> fp16
    ln_kernel<__half><<<MG, 256>>>(KV, lng_g, lng_b, Kn, SEQ_D, 2 * SEQ_D);
    ln_kernel<__half><<<MQ, 256>>>(query_pos, lnq_g, lnq_b, qn, POS_D, POS_D);

    // 3) Qh = qn @ Wq -> fp16
    gemm_h<__half, float, EPI_NONE><<<dim3(SEQ_D / 128, MQ / 128), blk>>>(
        qn, WqT, nullptr, nullptr, Qh, MQ, SEQ_D, POS_D,
        POS_D, POS_D, SEQ_D, 1.0f);

    // 4-6) fused attention -> attn fp16
    fused_attn<<<dim3(LQ / 128, BB * NH), blk, FA_SMEM>>>(Qh, Kn, VT, attn);

    // 7) x = Qh + attn @ Wo  (fp32 out)
    gemm_h<float, __half, EPI_RESID><<<dim3(SEQ_D / 128, MQ / 128), blk>>>(
        attn, WoT, nullptr, Qh, x, MQ, SEQ_D, SEQ_D,
        SEQ_D, SEQ_D, SEQ_D, 1.0f);

    // 8) xn = LN(x) -> fp16
    ln_kernel<__half><<<MQ, 256>>>(x, lnm_g, lnm_b, xn, SEQ_D, SEQ_D);

    // 9) hb = gelu(xn @ W1 + b1) -> fp16
    gemm_h<__half, float, EPI_GELU_BIAS><<<dim3(HD / 128, MQ / 128), blk>>>(
        xn, W1T, b1, nullptr, hb, MQ, HD, SEQ_D,
        SEQ_D, SEQ_D, HD, 1.0f);

    // 10) out = x + hb @ W2 + b2
    gemm_h<float, float, EPI_BIAS_RESID><<<dim3(SEQ_D / 128, MQ / 128), blk>>>(
        hb, W2T, b2, x, out, MQ, SEQ_D, HD,
        HD, HD, SEQ_D, 1.0f);
}

// round 16
// speedup vs baseline: 1.1502x; 1.0079x over previous
#include <cuda_runtime.h>
#include <cuda_fp16.h>
#include <math.h>
#include <stdint.h>

// Problem constants
#define BB      16
#define GRID_D  1024
#define SEQ_D   1024
#define POS_D   512
#define NH      16
#define HEAD    64
#define LQ      1024
#define TKV     256
#define MULT    4
#define EPSF    1e-5f

// ---------------- scratch (static device memory) ---------------
__device__ __half g_gridh[(size_t)BB * TKV * GRID_D];
__device__ float  g_KV  [(size_t)BB * TKV * 2 * SEQ_D];       // [4096][2048]: Kpre | V
__device__ __half g_Kn  [(size_t)BB * TKV * SEQ_D];
__device__ __half g_qn  [(size_t)BB * LQ * POS_D];
__device__ __half g_Qh  [(size_t)BB * LQ * SEQ_D];
__device__ __half g_attn[(size_t)BB * LQ * SEQ_D];
__device__ __half g_xh  [(size_t)BB * LQ * SEQ_D];            // fp16 residual x
__device__ __half g_xn  [(size_t)BB * LQ * SEQ_D];
__device__ __half g_h   [(size_t)BB * LQ * MULT * SEQ_D];
__device__ __half g_WkvT[(size_t)2 * SEQ_D * GRID_D];         // [2048][1024]: WkT | WvT
__device__ __half g_WqT [(size_t)SEQ_D * POS_D];
__device__ __half g_WoT [(size_t)SEQ_D * SEQ_D];
__device__ __half g_W1T [(size_t)MULT * SEQ_D * SEQ_D];
__device__ __half g_W2T [(size_t)SEQ_D * MULT * SEQ_D];
__device__ __half g_VT  [(size_t)BB * NH * HEAD * TKV];

// ---------------- helpers ----------------
__device__ __forceinline__ float gelu_f(float v) {
    float v3 = v * v * v;
    return 0.5f * v * (1.0f + tanhf(0.7978845608028654f * (v + 0.044715f * v3)));
}
__device__ __forceinline__ uint32_t sptr(const void* p) {
    uint32_t a;
    asm("{ .reg .u64 t; cvta.to.shared.u64 t, %1; cvt.u32.u64 %0, t; }" : "=r"(a) : "l"(p));
    return a;
}
__device__ __forceinline__ uint32_t pack2(float a, float b) {
    __half2 h = __float22half2_rn(make_float2(a, b));
    return *reinterpret_cast<uint32_t*>(&h);
}

#define CP_ASYNC16(dst, src) \
    asm volatile("cp.async.cg.shared.global [%0], [%1], 16;" \
                 :: "r"(dst), "l"(src) : "memory")
#define CP_COMMIT() asm volatile("cp.async.commit_group;" ::: "memory")
#define CP_WAIT0()  asm volatile("cp.async.wait_group 0;" ::: "memory")

#define LDMX4(r0, r1, r2, r3, addr) \
    asm volatile("ldmatrix.sync.aligned.m8n8.x4.shared.b16 {%0,%1,%2,%3}, [%4];" \
                 : "=r"(r0), "=r"(r1), "=r"(r2), "=r"(r3) : "r"(addr))

#define MMA16816(d, a, b) \
    asm volatile("mma.sync.aligned.m16n8k16.row.col.f32.f16.f16.f32 " \
                 "{%0,%1,%2,%3}, {%4,%5,%6,%7}, {%8,%9}, {%0,%1,%2,%3};" \
                 : "+f"((d)[0]), "+f"((d)[1]), "+f"((d)[2]), "+f"((d)[3]) \
                 : "r"((a)[0]), "r"((a)[1]), "r"((a)[2]), "r"((a)[3]), \
                   "r"((b)[0]), "r"((b)[1]))

enum { EPI_NONE = 0, EPI_RESID = 1, EPI_GELU_BIAS = 2, EPI_BIAS_RESID = 3 };

// =================================================================
// fp16 tensor-core GEMM (NT): C[M,N] = alpha * A[M,K] @ BT[N,K]^T (+epi)
// Round-14-proven config: BM=128, BN=128, BK=32; 8 warps of 32x64;
// 2-stage cp.async; static SMEM 40KB; 2 CTAs/SM.
// TR = residual element type (float or __half).
// =================================================================
template <typename TC, typename TR, int EPI>
__global__ __launch_bounds__(256, 2)
void gemm_h(const __half* __restrict__ A, const __half* __restrict__ BT,
            const float* __restrict__ bias, const TR* __restrict__ res,
            TC* __restrict__ C,
            int M, int N, int K, int lda, int ldb, int ldc, float alpha)
{
    constexpr int BM = 128, BN = 128, BK = 32;
    constexpr int STR = 40;

    __shared__ __half As[2][BM][STR];
    __shared__ __half Bs[2][BN][STR];

    const int tid  = threadIdx.x;
    const int lane = tid & 31;
    const int warp = tid >> 5;
    const int wm   = warp >> 1;
    const int wn   = warp & 1;
    const int m0   = blockIdx.y * BM;
    const int n0   = blockIdx.x * BN;

    float acc[2][8][4];
#pragma unroll
    for (int mt = 0; mt < 2; mt++)
#pragma unroll
        for (int nt = 0; nt < 8; nt++)
#pragma unroll
            for (int j = 0; j < 4; j++) acc[mt][nt][j] = 0.0f;

    auto issue = [&](int buf, int k0) {
#pragma unroll
        for (int i = 0; i < 2; i++) {
            int s = tid + i * 256, r = s >> 2, cs = s & 3;
            CP_ASYNC16(sptr(&As[buf][r][cs * 8]),
                       A + (size_t)(m0 + r) * lda + k0 + cs * 8);
        }
#pragma unroll
        for (int i = 0; i < 2; i++) {
            int s = tid + i * 256, r = s >> 2, cs = s & 3;
            CP_ASYNC16(sptr(&Bs[buf][r][cs * 8]),
                       BT + (size_t)(n0 + r) * ldb + k0 + cs * 8);
        }
        CP_COMMIT();
    };

    const int lr = lane & 15;
    const int lc = lane >> 4;

    auto compute = [&](int buf) {
#pragma unroll
        for (int ks = 0; ks < 2; ks++) {
            uint32_t af[2][4];
#pragma unroll
            for (int mt = 0; mt < 2; mt++) {
                uint32_t ad = sptr(&As[buf][wm * 32 + mt * 16 + lr][ks * 16 + lc * 8]);
                LDMX4(af[mt][0], af[mt][1], af[mt][2], af[mt][3], ad);
            }
            uint32_t bf[8][2];
#pragma unroll
            for (int np = 0; np < 4; np++) {
                uint32_t r0, r1, r2, r3;
                uint32_t bd = sptr(&Bs[buf][wn * 64 + np * 16 + lr][ks * 16 + lc * 8]);
                LDMX4(r0, r1, r2, r3, bd);
                bf[np * 2 + 0][0] = r0; bf[np * 2 + 0][1] = r2;
                bf[np * 2 + 1][0] = r1; bf[np * 2 + 1][1] = r3;
            }
#pragma unroll
            for (int mt = 0; mt < 2; mt++)
#pragma unroll
                for (int nt = 0; nt < 8; nt++)
                    MMA16816(acc[mt][nt], af[mt], bf[nt]);
        }
    };

    const int nk = K / BK;
    issue(0, 0);
    for (int it = 0; it < nk; ++it) {
        const int cur = it & 1;
        CP_WAIT0();
        __syncthreads();
        if (it + 1 < nk) issue(cur ^ 1, (it + 1) * BK);
        compute(cur);
    }

    const int g4 = lane >> 2, t4 = lane & 3;
#pragma unroll
    for (int mt = 0; mt < 2; mt++) {
#pragma unroll
        for (int nt = 0; nt < 8; nt++) {
            int r = m0 + wm * 32 + mt * 16 + g4;
            int c = n0 + wn * 64 + nt * 8 + 2 * t4;
#pragma unroll
            for (int half = 0; half < 2; half++) {
                int rr = r + half * 8;
                float2 v = make_float2(acc[mt][nt][half * 2 + 0] * alpha,
                                       acc[mt][nt][half * 2 + 1] * alpha);
                if (EPI == EPI_GELU_BIAS) {
                    float2 bv = *(const float2*)(bias + c);
                    v.x = gelu_f(v.x + bv.x);
                    v.y = gelu_f(v.y + bv.y);
                } else if (EPI == EPI_RESID || EPI == EPI_BIAS_RESID) {
                    float2 rv;
                    if (sizeof(TR) == 2) {
                        __half2 hh = *(const __half2*)((const __half*)(const void*)res
                                        + (size_t)rr * ldc + c);
                        rv = __half22float2(hh);
                    } else {
                        rv = *(const float2*)((const float*)(const void*)res
                                        + (size_t)rr * ldc + c);
                    }
                    if (EPI == EPI_BIAS_RESID) {
                        float2 bv = *(const float2*)(bias + c);
                        rv.x += bv.x; rv.y += bv.y;
                    }
                    v.x += rv.x; v.y += rv.y;
                }
                if (sizeof(TC) == 4) {
                    *(float2*)((float*)(void*)C + (size_t)rr * ldc + c) = v;
                } else {
                    __half2 h = __float22half2_rn(v);
                    *(__half2*)((__half*)(void*)C + (size_t)rr * ldc + c) = h;
                }
            }
        }
    }
}

// =================================================================
// Fused attention (round-14-proven; Q fp16)
// =================================================================
#define FA_QS_OFF 0
#define FA_KS_OFF (128 * 72)
#define FA_VS_OFF (128 * 72 + 256 * 72)
#define FA_SMEM   ((128 * 72 + 256 * 72 + 64 * 264) * 2)

__global__ __launch_bounds__(256, 1)
void fused_attn(const __half* __restrict__ Q, const __half* __restrict__ Kn,
                const __half* __restrict__ VT, __half* __restrict__ attn)
{
    extern __shared__ __half fsm[];
    __half* Qs = fsm + FA_QS_OFF;
    __half* Ks = fsm + FA_KS_OFF;
    __half* Vs = fsm + FA_VS_OFF;

    const int tid  = threadIdx.x;
    const int lane = tid & 31;
    const int warp = tid >> 5;
    const int q0   = blockIdx.x * 128;
    const int bh   = blockIdx.y;
    const int b    = bh >> 4;
    const int h    = bh & 15;

    const __half* Qg = Q  + ((size_t)b * LQ + q0) * SEQ_D + h * HEAD;
    const __half* Kg = Kn + (size_t)b * TKV * SEQ_D + h * HEAD;
    const __half* Vg = VT + (size_t)bh * HEAD * TKV;

    for (int s = tid; s < 1024; s += 256) {
        int r = s >> 3, c8 = (s & 7) * 8;
        *(uint4*)&Qs[r * 72 + c8] = *(const uint4*)(Qg + (size_t)r * SEQ_D + c8);
    }
    for (int s = tid; s < 2048; s += 256) {
        int r = s >> 3, c8 = (s & 7) * 8;
        *(uint4*)&Ks[r * 72 + c8] = *(const uint4*)(Kg + (size_t)r * SEQ_D + c8);
    }
    for (int s = tid; s < 2048; s += 256) {
        int r = s >> 5, c8 = (s & 31) * 8;
        *(uint4*)&Vs[r * 264 + c8] = *(const uint4*)(Vg + (size_t)r * TKV + c8);
    }
    __syncthreads();

    const int lr = lane & 15;
    const int lc = lane >> 4;
    const int g4 = lane >> 2;
    const int t4 = lane & 3;

    float acc[32][4];
#pragma unroll
    for (int nt = 0; nt < 32; nt++)
#pragma unroll
        for (int j = 0; j < 4; j++) acc[nt][j] = 0.0f;

#pragma unroll
    for (int ks = 0; ks < 4; ks++) {
        uint32_t af[4];
        LDMX4(af[0], af[1], af[2], af[3],
              sptr(&Qs[(warp * 16 + lr) * 72 + ks * 16 + lc * 8]));
#pragma unroll
        for (int np = 0; np < 16; np++) {
            uint32_t r0, r1, r2, r3;
            LDMX4(r0, r1, r2, r3,
                  sptr(&Ks[(np * 16 + lr) * 72 + ks * 16 + lc * 8]));
            uint32_t b0[2] = { r0, r2 };
            uint32_t b1[2] = { r1, r3 };
            MMA16816(acc[np * 2 + 0], af, b0);
            MMA16816(acc[np * 2 + 1], af, b1);
        }
    }

    float mx0 = -1e30f, mx1 = -1e30f;
#pragma unroll
    for (int nt = 0; nt < 32; nt++) {
#pragma unroll
        for (int j = 0; j < 4; j++) acc[nt][j] *= 0.125f;
        mx0 = fmaxf(mx0, fmaxf(acc[nt][0], acc[nt][1]));
        mx1 = fmaxf(mx1, fmaxf(acc[nt][2], acc[nt][3]));
    }
    mx0 = fmaxf(mx0, __shfl_xor_sync(0xffffffffu, mx0, 1));
    mx0 = fmaxf(mx0, __shfl_xor_sync(0xffffffffu, mx0, 2));
    mx1 = fmaxf(mx1, __shfl_xor_sync(0xffffffffu, mx1, 1));
    mx1 = fmaxf(mx1, __shfl_xor_sync(0xffffffffu, mx1, 2));

    float s0 = 0.0f, s1 = 0.0f;
#pragma unroll
    for (int nt = 0; nt < 32; nt++) {
        acc[nt][0] = __expf(acc[nt][0] - mx0);
        acc[nt][1] = __expf(acc[nt][1] - mx0);
        acc[nt][2] = __expf(acc[nt][2] - mx1);
        acc[nt][3] = __expf(acc[nt][3] - mx1);
        s0 += acc[nt][0] + acc[nt][1];
        s1 += acc[nt][2] + acc[nt][3];
    }
    s0 += __shfl_xor_sync(0xffffffffu, s0, 1);
    s0 += __shfl_xor_sync(0xffffffffu, s0, 2);
    s1 += __shfl_xor_sync(0xffffffffu, s1, 1);
    s1 += __shfl_xor_sync(0xffffffffu, s1, 2);
    const float inv0 = 1.0f / s0;
    const float inv1 = 1.0f / s1;

    float oacc[8][4];
#pragma unroll
    for (int nt = 0; nt < 8; nt++)
#pragma unroll
        for (int j = 0; j < 4; j++) oacc[nt][j] = 0.0f;

#pragma unroll
    for (int kc = 0; kc < 16; kc++) {
        uint32_t af[4];
        af[0] = pack2(acc[2 * kc][0],     acc[2 * kc][1]);
        af[1] = pack2(acc[2 * kc][2],     acc[2 * kc][3]);
        af[2] = pack2(acc[2 * kc + 1][0], acc[2 * kc + 1][1]);
        af[3] = pack2(acc[2 * kc + 1][2], acc[2 * kc + 1][3]);
#pragma unroll
        for (int np = 0; np < 4; np++) {
            uint32_t r0, r1, r2, r3;
            LDMX4(r0, r1, r2, r3,
                  sptr(&Vs[(np * 16 + lr) * 264 + kc * 16 + lc * 8]));
            uint32_t b0[2] = { r0, r2 };
            uint32_t b1[2] = { r1, r3 };
            MMA16816(oacc[np * 2 + 0], af, b0);
            MMA16816(oacc[np * 2 + 1], af, b1);
        }
    }

    __half* Og = attn + ((size_t)b * LQ + q0 + warp * 16) * SEQ_D + h * HEAD;
#pragma unroll
    for (int nt = 0; nt < 8; nt++) {
        int c = nt * 8 + 2 * t4;
        float2 v0 = make_float2(oacc[nt][0] * inv0, oacc[nt][1] * inv0);
        float2 v1 = make_float2(oacc[nt][2] * inv1, oacc[nt][3] * inv1);
        *(__half2*)(Og + (size_t)g4 * SEQ_D + c)       = __float22half2_rn(v0);
        *(__half2*)(Og + (size_t)(g4 + 8) * SEQ_D + c) = __float22half2_rn(v1);
    }
}

// ---------------- fp32 -> fp16 elementwise ----------------
__global__ __launch_bounds__(256)
void f2h_kernel(const float* __restrict__ X, __half* __restrict__ Y)
{
    size_t s = (size_t)blockIdx.x * 256 + threadIdx.x;
    const float* p = X + s * 8;
    float4 v0 = *(const float4*)p, v1 = *(const float4*)(p + 4);
    uint4 u = { pack2(v0.x, v0.y), pack2(v0.z, v0.w),
                pack2(v1.x, v1.y), pack2(v1.z, v1.w) };
    *(uint4*)(Y + s * 8) = u;
}

// ---------------- weight transpose ----------------
__global__ __launch_bounds__(256)
void transpose_kernel(const float* __restrict__ W, __half* __restrict__ WT,
                      int K, int N)
{
    __shared__ float t[32][33];
    int n0 = blockIdx.x * 32, k0 = blockIdx.y * 32;
    int tx = threadIdx.x & 31, ty = threadIdx.x >> 5;
#pragma unroll
    for (int i = 0; i < 32; i += 8)
        t[ty + i][tx] = W[(size_t)(k0 + ty + i) * N + n0 + tx];
    __syncthreads();
#pragma unroll
    for (int i = 0; i < 32; i += 8)
        WT[(size_t)(n0 + ty + i) * K + k0 + tx] = __float2half_rn(t[tx][ty + i]);
}

// ---------------- V transpose per head (reads V half of KV) ----------------
__global__ __launch_bounds__(256)
void vt_kernel(const float* __restrict__ KV, __half* __restrict__ VT)
{
    __shared__ float t[32][33];
    int t0 = blockIdx.x * 32;
    int d0 = blockIdx.y * 32;
    int bh = blockIdx.z;
    int b = bh / NH, h = bh % NH;
    int tx = threadIdx.x & 31, ty = threadIdx.x >> 5;
#pragma unroll
    for (int i = 0; i < 32; i += 8)
        t[ty + i][tx] = KV[((size_t)b * TKV + t0 + ty + i) * (2 * SEQ_D)
                           + SEQ_D + h * HEAD + d0 + tx];
    __syncthreads();
#pragma unroll
    for (int i = 0; i < 32; i += 8)
        VT[((size_t)bh * HEAD + d0 + ty + i) * TKV + t0 + tx] =
            __float2half_rn(t[tx][ty + i]);
}

// ---------------- LayerNorm (templated in/out; ldx = input stride) -------
template <typename TIN, typename TOUT>
__global__ __launch_bounds__(256)
void ln_kernel(const TIN* __restrict__ X, const float* __restrict__ g,
               const float* __restrict__ b, TOUT* __restrict__ Y, int D, int ldx)
{
    long row = blockIdx.x;
    const float4* g4 = (const float4*)g;
    const float4* b4 = (const float4*)b;
    int n4 = D >> 2;

    float s = 0.0f, s2 = 0.0f;
    for (int i = threadIdx.x; i < n4; i += 256) {
        float4 v;
        if (sizeof(TIN) == 4) {
            v = ((const float4*)(const void*)(X + row * (long)ldx))[i];
        } else {
            uint2 u = ((const uint2*)(const void*)(X + row * (long)ldx))[i];
            float2 lo = __half22float2(*(__half2*)&u.x);
            float2 hi = __half22float2(*(__half2*)&u.y);
            v = make_float4(lo.x, lo.y, hi.x, hi.y);
        }
        s  += v.x + v.y + v.z + v.w;
        s2 += v.x * v.x + v.y * v.y + v.z * v.z + v.w * v.w;
    }
#pragma unroll
    for (int o = 16; o; o >>= 1) {
        s  += __shfl_xor_sync(0xffffffffu, s, o);
        s2 += __shfl_xor_sync(0xffffffffu, s2, o);
    }
    __shared__ float sh[16];
    int w = threadIdx.x >> 5, lane = threadIdx.x & 31;
    if (lane == 0) { sh[w] = s; sh[w + 8] = s2; }
    __syncthreads();
    if (threadIdx.x < 32) {
        float a = (threadIdx.x < 8) ? sh[threadIdx.x] : 0.0f;
        float c = (threadIdx.x < 8) ? sh[threadIdx.x + 8] : 0.0f;
#pragma unroll
        for (int o = 16; o; o >>= 1) {
            a += __shfl_xor_sync(0xffffffffu, a, o);
            c += __shfl_xor_sync(0xffffffffu, c, o);
        }
        if (threadIdx.x == 0) { sh[0] = a; sh[1] = c; }
    }
    __syncthreads();
    float invD = 1.0f / (float)D;
    float mu   = sh[0] * invD;
    float var  = sh[1] * invD - mu * mu;
    float rstd = rsqrtf(var + EPSF);

    for (int i = threadIdx.x; i < n4; i += 256) {
        float4 v;
        if (sizeof(TIN) == 4) {
            v = ((const float4*)(const void*)(X + row * (long)ldx))[i];
        } else {
            uint2 u = ((const uint2*)(const void*)(X + row * (long)ldx))[i];
            float2 lo = __half22float2(*(__half2*)&u.x);
            float2 hi = __half22float2(*(__half2*)&u.y);
            v = make_float4(lo.x, lo.y, hi.x, hi.y);
        }
        float4 gg = g4[i], bb = b4[i];
        v.x = (v.x - mu) * rstd * gg.x + bb.x;
        v.y = (v.y - mu) * rstd * gg.y + bb.y;
        v.z = (v.z - mu) * rstd * gg.z + bb.z;
        v.w = (v.w - mu) * rstd * gg.w + bb.w;
        if (sizeof(TOUT) == 4) {
            ((float4*)(void*)(Y + row * (long)D))[i] = v;
        } else {
            uint2 u = { pack2(v.x, v.y), pack2(v.z, v.w) };
            ((uint2*)(void*)(Y + row * (long)D))[i] = u;
        }
    }
}

// ---------------- launch ----------------
extern "C" void kernel_launch(void* const* d_in, const int* in_sizes, int n_in,
                              void* d_out, int out_size)
{
    const float* grid      = (const float*)d_in[0];
    const float* query_pos = (const float*)d_in[1];
    const float* Wq        = (const float*)d_in[2];
    const float* Wk        = (const float*)d_in[3];
    const float* Wv        = (const float*)d_in[4];
    const float* Wo        = (const float*)d_in[5];
    const float* lng_g     = (const float*)d_in[6];
    const float* lng_b     = (const float*)d_in[7];
    const float* lnq_g     = (const float*)d_in[8];
    const float* lnq_b     = (const float*)d_in[9];
    const float* lnm_g     = (const float*)d_in[10];
    const float* lnm_b     = (const float*)d_in[11];
    const float* W1        = (const float*)d_in[12];
    const float* b1        = (const float*)d_in[13];
    const float* W2        = (const float*)d_in[14];
    const float* b2        = (const float*)d_in[15];
    float* out = (float*)d_out;

    float *KV;
    __half *gridh, *Kn, *qn, *Qh, *attn, *xh, *xn, *hb;
    __half *WkvT, *WqT, *WoT, *W1T, *W2T, *VT;
    cudaGetSymbolAddress((void**)&gridh, g_gridh);
    cudaGetSymbolAddress((void**)&KV,   g_KV);
    cudaGetSymbolAddress((void**)&Kn,   g_Kn);
    cudaGetSymbolAddress((void**)&qn,   g_qn);
    cudaGetSymbolAddress((void**)&Qh,   g_Qh);
    cudaGetSymbolAddress((void**)&attn, g_attn);
    cudaGetSymbolAddress((void**)&xh,   g_xh);
    cudaGetSymbolAddress((void**)&xn,   g_xn);
    cudaGetSymbolAddress((void**)&hb,   g_h);
    cudaGetSymbolAddress((void**)&WkvT, g_WkvT);
    cudaGetSymbolAddress((void**)&WqT,  g_WqT);
    cudaGetSymbolAddress((void**)&WoT,  g_WoT);
    cudaGetSymbolAddress((void**)&W1T,  g_W1T);
    cudaGetSymbolAddress((void**)&W2T,  g_W2T);
    cudaGetSymbolAddress((void**)&VT,   g_VT);

    cudaFuncSetAttribute(fused_attn,
        cudaFuncAttributeMaxDynamicSharedMemorySize, FA_SMEM);

    dim3 blk(256);
    const int MG = BB * TKV;       // 4096
    const int MQ = BB * LQ;        // 16384
    const int HD = MULT * SEQ_D;   // 4096

    // 0) fp16 conversions / transposes
    f2h_kernel<<<(MG * GRID_D) / (256 * 8), blk>>>(grid, gridh);
    transpose_kernel<<<dim3(SEQ_D / 32, GRID_D / 32), blk>>>(Wk, WkvT, GRID_D, SEQ_D);
    transpose_kernel<<<dim3(SEQ_D / 32, GRID_D / 32), blk>>>(
        Wv, WkvT + (size_t)SEQ_D * GRID_D, GRID_D, SEQ_D);
    transpose_kernel<<<dim3(SEQ_D / 32, POS_D / 32),  blk>>>(Wq, WqT, POS_D, SEQ_D);
    transpose_kernel<<<dim3(SEQ_D / 32, SEQ_D / 32),  blk>>>(Wo, WoT, SEQ_D, SEQ_D);
    transpose_kernel<<<dim3(HD / 32, SEQ_D / 32),     blk>>>(W1, W1T, SEQ_D, HD);
    transpose_kernel<<<dim3(SEQ_D / 32, HD / 32),     blk>>>(W2, W2T, HD, SEQ_D);

    // 1) KV = grid @ [Wk | Wv]  (merged, N=2048)
    gemm_h<float, float, EPI_NONE><<<dim3(2 * SEQ_D / 128, MG / 128), blk>>>(
        gridh, WkvT, nullptr, nullptr, KV, MG, 2 * SEQ_D, GRID_D,
        GRID_D, GRID_D, 2 * SEQ_D, 1.0f);

    // 1b) VT from V half of KV
    vt_kernel<<<dim3(TKV / 32, HEAD / 32, BB * NH), blk>>>(KV, VT);

    // 2) Kn = LN(KV[:, :1024]) -> fp16 ; qn = LN(query_pos) -> fp16
    ln_kernel<float, __half><<<MG, 256>>>(KV, lng_g, lng_b, Kn, SEQ_D, 2 * SEQ_D);
    ln_kernel<float, __half><<<MQ, 256>>>(query_pos, lnq_g, lnq_b, qn, POS_D, POS_D);

    // 3) Qh = qn @ Wq -> fp16
    gemm_h<__half, float, EPI_NONE><<<dim3(SEQ_D / 128, MQ / 128), blk>>>(
        qn, WqT, nullptr, nullptr, Qh, MQ, SEQ_D, POS_D,
        POS_D, POS_D, SEQ_D, 1.0f);

    // 4-6) fused attention -> attn fp16
    fused_attn<<<dim3(LQ / 128, BB * NH), blk, FA_SMEM>>>(Qh, Kn, VT, attn);

    // 7) xh = Qh + attn @ Wo  (fp16 out)
    gemm_h<__half, __half, EPI_RESID><<<dim3(SEQ_D / 128, MQ / 128), blk>>>(
        attn, WoT, nullptr, Qh, xh, MQ, SEQ_D, SEQ_D,
        SEQ_D, SEQ_D, SEQ_D, 1.0f);

    // 8) xn = LN(xh) -> fp16
    ln_kernel<__half, __half><<<MQ, 256>>>(xh, lnm_g, lnm_b, xn, SEQ_D, SEQ_D);

    // 9) hb = gelu(xn @ W1 + b1) -> fp16
    gemm_h<__half, float, EPI_GELU_BIAS><<<dim3(HD / 128, MQ / 128), blk>>>(
        xn, W1T, b1, nullptr, hb, MQ, HD, SEQ_D,
        SEQ_D, SEQ_D, HD, 1.0f);

    // 10) out = xh + hb @ W2 + b2  (fp32 out)
    gemm_h<float, __half, EPI_BIAS_RESID><<<dim3(SEQ_D / 128, MQ / 128), blk>>>(
        hb, W2T, b2, xh, out, MQ, SEQ_D, HD,
        HD, HD, SEQ_D, 1.0f);
}

// round 17
// speedup vs baseline: 1.2817x; 1.1143x over previous
#include <cuda_runtime.h>
#include <cuda_fp16.h>
#include <math.h>
#include <stdint.h>

// Problem constants
#define BB      16
#define GRID_D  1024
#define SEQ_D   1024
#define POS_D   512
#define NH      16
#define HEAD    64
#define LQ      1024
#define TKV     256
#define MULT    4
#define EPSF    1e-5f

// ---------------- scratch (static device memory) ---------------
__device__ __half g_gridh[(size_t)BB * TKV * GRID_D];
__device__ float  g_KV  [(size_t)BB * TKV * 2 * SEQ_D];       // [4096][2048]: Kpre | V
__device__ __half g_Kn  [(size_t)BB * TKV * SEQ_D];
__device__ __half g_qn  [(size_t)BB * LQ * POS_D];
__device__ __half g_Qh  [(size_t)BB * LQ * SEQ_D];
__device__ __half g_attn[(size_t)BB * LQ * SEQ_D];
__device__ __half g_xh  [(size_t)BB * LQ * SEQ_D];            // fp16 residual x
__device__ __half g_xn  [(size_t)BB * LQ * SEQ_D];
__device__ __half g_h   [(size_t)BB * LQ * MULT * SEQ_D];
__device__ __half g_WkvT[(size_t)2 * SEQ_D * GRID_D];         // [2048][1024]: WkT | WvT
__device__ __half g_WqT [(size_t)SEQ_D * POS_D];
__device__ __half g_WoT [(size_t)SEQ_D * SEQ_D];
__device__ __half g_W1T [(size_t)MULT * SEQ_D * SEQ_D];
__device__ __half g_W2T [(size_t)SEQ_D * MULT * SEQ_D];
__device__ __half g_VT  [(size_t)BB * NH * HEAD * TKV];

// ---------------- helpers ----------------
__device__ __forceinline__ float gelu_f(float v) {
    float v3 = v * v * v;
    return 0.5f * v * (1.0f + tanhf(0.7978845608028654f * (v + 0.044715f * v3)));
}
__device__ __forceinline__ uint32_t sptr(const void* p) {
    uint32_t a;
    asm("{ .reg .u64 t; cvta.to.shared.u64 t, %1; cvt.u32.u64 %0, t; }" : "=r"(a) : "l"(p));
    return a;
}
__device__ __forceinline__ uint32_t pack2(float a, float b) {
    __half2 h = __float22half2_rn(make_float2(a, b));
    return *reinterpret_cast<uint32_t*>(&h);
}

#define CP_ASYNC16(dst, src) \
    asm volatile("cp.async.cg.shared.global [%0], [%1], 16;" \
                 :: "r"(dst), "l"(src) : "memory")
#define CP_COMMIT() asm volatile("cp.async.commit_group;" ::: "memory")
#define CP_WAIT0()  asm volatile("cp.async.wait_group 0;" ::: "memory")

#define LDMX4(r0, r1, r2, r3, addr) \
    asm volatile("ldmatrix.sync.aligned.m8n8.x4.shared.b16 {%0,%1,%2,%3}, [%4];" \
                 : "=r"(r0), "=r"(r1), "=r"(r2), "=r"(r3) : "r"(addr))

#define MMA16816(d, a, b) \
    asm volatile("mma.sync.aligned.m16n8k16.row.col.f32.f16.f16.f32 " \
                 "{%0,%1,%2,%3}, {%4,%5,%6,%7}, {%8,%9}, {%0,%1,%2,%3};" \
                 : "+f"((d)[0]), "+f"((d)[1]), "+f"((d)[2]), "+f"((d)[3]) \
                 : "r"((a)[0]), "r"((a)[1]), "r"((a)[2]), "r"((a)[3]), \
                   "r"((b)[0]), "r"((b)[1]))

enum { EPI_NONE = 0, EPI_RESID = 1, EPI_GELU_BIAS = 2, EPI_BIAS_RESID = 3 };

// =================================================================
// fp16 tensor-core GEMM (NT): C[M,N] = alpha * A[M,K] @ BT[N,K]^T (+epi)
// BM=128, BN=128, BK=64; 8 warps of 32x64; 2-stage cp.async;
// dynamic SMEM 73728 B/CTA; 2 CTAs/SM (147 KB of 227 KB).
// Identical MMA count & accumulation order to the BK=32 version;
// only the barrier count per CTA is halved.
// TR = residual element type (float or __half).
// =================================================================
#define GH_STR  72                             // halves per smem row (64 + 8 pad)
#define GH_BUF  (128 * GH_STR)                 // halves per A (or B) buffer
#define GH_BOFF (2 * GH_BUF)                   // B region start (halves)
#define GH_SMEM (4 * GH_BUF * 2)               // 73728 bytes

template <typename TC, typename TR, int EPI>
__global__ __launch_bounds__(256, 2)
void gemm_h(const __half* __restrict__ A, const __half* __restrict__ BT,
            const float* __restrict__ bias, const TR* __restrict__ res,
            TC* __restrict__ C,
            int M, int N, int K, int lda, int ldb, int ldc, float alpha)
{
    constexpr int BM = 128, BN = 128, BK = 64;
    extern __shared__ __half gsm[];

    const int tid  = threadIdx.x;
    const int lane = tid & 31;
    const int warp = tid >> 5;
    const int wm   = warp >> 1;
    const int wn   = warp & 1;
    const int m0   = blockIdx.y * BM;
    const int n0   = blockIdx.x * BN;

    float acc[2][8][4];
#pragma unroll
    for (int mt = 0; mt < 2; mt++)
#pragma unroll
        for (int nt = 0; nt < 8; nt++)
#pragma unroll
            for (int j = 0; j < 4; j++) acc[mt][nt][j] = 0.0f;

    auto issue = [&](int buf, int k0) {
        __half* As = gsm + buf * GH_BUF;
        __half* Bs = gsm + GH_BOFF + buf * GH_BUF;
#pragma unroll
        for (int i = 0; i < 4; i++) {          // A: 1024 16B segs
            int s = tid + i * 256, r = s >> 3, cs = s & 7;
            CP_ASYNC16(sptr(As + r * GH_STR + cs * 8),
                       A + (size_t)(m0 + r) * lda + k0 + cs * 8);
        }
#pragma unroll
        for (int i = 0; i < 4; i++) {          // B: 1024 16B segs
            int s = tid + i * 256, r = s >> 3, cs = s & 7;
            CP_ASYNC16(sptr(Bs + r * GH_STR + cs * 8),
                       BT + (size_t)(n0 + r) * ldb + k0 + cs * 8);
        }
        CP_COMMIT();
    };

    const int lr = lane & 15;
    const int lc = lane >> 4;

    auto compute = [&](int buf) {
        const __half* As = gsm + buf * GH_BUF;
        const __half* Bs = gsm + GH_BOFF + buf * GH_BUF;
#pragma unroll
        for (int ks = 0; ks < 4; ks++) {
            uint32_t af[2][4];
#pragma unroll
            for (int mt = 0; mt < 2; mt++) {
                uint32_t ad = sptr(As + (wm * 32 + mt * 16 + lr) * GH_STR
                                      + ks * 16 + lc * 8);
                LDMX4(af[mt][0], af[mt][1], af[mt][2], af[mt][3], ad);
            }
            uint32_t bf[8][2];
#pragma unroll
            for (int np = 0; np < 4; np++) {
                uint32_t r0, r1, r2, r3;
                uint32_t bd = sptr(Bs + (wn * 64 + np * 16 + lr) * GH_STR
                                      + ks * 16 + lc * 8);
                LDMX4(r0, r1, r2, r3, bd);
                bf[np * 2 + 0][0] = r0; bf[np * 2 + 0][1] = r2;
                bf[np * 2 + 1][0] = r1; bf[np * 2 + 1][1] = r3;
            }
#pragma unroll
            for (int mt = 0; mt < 2; mt++)
#pragma unroll
                for (int nt = 0; nt < 8; nt++)
                    MMA16816(acc[mt][nt], af[mt], bf[nt]);
        }
    };

    const int nk = K / BK;
    issue(0, 0);
    for (int it = 0; it < nk; ++it) {
        const int cur = it & 1;
        CP_WAIT0();
        __syncthreads();
        if (it + 1 < nk) issue(cur ^ 1, (it + 1) * BK);
        compute(cur);
    }

    const int g4 = lane >> 2, t4 = lane & 3;
#pragma unroll
    for (int mt = 0; mt < 2; mt++) {
#pragma unroll
        for (int nt = 0; nt < 8; nt++) {
            int r = m0 + wm * 32 + mt * 16 + g4;
            int c = n0 + wn * 64 + nt * 8 + 2 * t4;
#pragma unroll
            for (int half = 0; half < 2; half++) {
                int rr = r + half * 8;
                float2 v = make_float2(acc[mt][nt][half * 2 + 0] * alpha,
                                       acc[mt][nt][half * 2 + 1] * alpha);
                if (EPI == EPI_GELU_BIAS) {
                    float2 bv = *(const float2*)(bias + c);
                    v.x = gelu_f(v.x + bv.x);
                    v.y = gelu_f(v.y + bv.y);
                } else if (EPI == EPI_RESID || EPI == EPI_BIAS_RESID) {
                    float2 rv;
                    if (sizeof(TR) == 2) {
                        __half2 hh = *(const __half2*)((const __half*)(const void*)res
                                        + (size_t)rr * ldc + c);
                        rv = __half22float2(hh);
                    } else {
                        rv = *(const float2*)((const float*)(const void*)res
                                        + (size_t)rr * ldc + c);
                    }
                    if (EPI == EPI_BIAS_RESID) {
                        float2 bv = *(const float2*)(bias + c);
                        rv.x += bv.x; rv.y += bv.y;
                    }
                    v.x += rv.x; v.y += rv.y;
                }
                if (sizeof(TC) == 4) {
                    *(float2*)((float*)(void*)C + (size_t)rr * ldc + c) = v;
                } else {
                    __half2 h = __float22half2_rn(v);
                    *(__half2*)((__half*)(void*)C + (size_t)rr * ldc + c) = h;
                }
            }
        }
    }
}

// =================================================================
// Fused attention (round-16-proven; Q fp16)
// =================================================================
#define FA_QS_OFF 0
#define FA_KS_OFF (128 * 72)
#define FA_VS_OFF (128 * 72 + 256 * 72)
#define FA_SMEM   ((128 * 72 + 256 * 72 + 64 * 264) * 2)

__global__ __launch_bounds__(256, 1)
void fused_attn(const __half* __restrict__ Q, const __half* __restrict__ Kn,
                const __half* __restrict__ VT, __half* __restrict__ attn)
{
    extern __shared__ __half fsm[];
    __half* Qs = fsm + FA_QS_OFF;
    __half* Ks = fsm + FA_KS_OFF;
    __half* Vs = fsm + FA_VS_OFF;

    const int tid  = threadIdx.x;
    const int lane = tid & 31;
    const int warp = tid >> 5;
    const int q0   = blockIdx.x * 128;
    const int bh   = blockIdx.y;
    const int b    = bh >> 4;
    const int h    = bh & 15;

    const __half* Qg = Q  + ((size_t)b * LQ + q0) * SEQ_D + h * HEAD;
    const __half* Kg = Kn + (size_t)b * TKV * SEQ_D + h * HEAD;
    const __half* Vg = VT + (size_t)bh * HEAD * TKV;

    for (int s = tid; s < 1024; s += 256) {
        int r = s >> 3, c8 = (s & 7) * 8;
        *(uint4*)&Qs[r * 72 + c8] = *(const uint4*)(Qg + (size_t)r * SEQ_D + c8);
    }
    for (int s = tid; s < 2048; s += 256) {
        int r = s >> 3, c8 = (s & 7) * 8;
        *(uint4*)&Ks[r * 72 + c8] = *(const uint4*)(Kg + (size_t)r * SEQ_D + c8);
    }
    for (int s = tid; s < 2048; s += 256) {
        int r = s >> 5, c8 = (s & 31) * 8;
        *(uint4*)&Vs[r * 264 + c8] = *(const uint4*)(Vg + (size_t)r * TKV + c8);
    }
    __syncthreads();

    const int lr = lane & 15;
    const int lc = lane >> 4;
    const int g4 = lane >> 2;
    const int t4 = lane & 3;

    float acc[32][4];
#pragma unroll
    for (int nt = 0; nt < 32; nt++)
#pragma unroll
        for (int j = 0; j < 4; j++) acc[nt][j] = 0.0f;

#pragma unroll
    for (int ks = 0; ks < 4; ks++) {
        uint32_t af[4];
        LDMX4(af[0], af[1], af[2], af[3],
              sptr(&Qs[(warp * 16 + lr) * 72 + ks * 16 + lc * 8]));
#pragma unroll
        for (int np = 0; np < 16; np++) {
            uint32_t r0, r1, r2, r3;
            LDMX4(r0, r1, r2, r3,
                  sptr(&Ks[(np * 16 + lr) * 72 + ks * 16 + lc * 8]));
            uint32_t b0[2] = { r0, r2 };
            uint32_t b1[2] = { r1, r3 };
            MMA16816(acc[np * 2 + 0], af, b0);
            MMA16816(acc[np * 2 + 1], af, b1);
        }
    }

    float mx0 = -1e30f, mx1 = -1e30f;
#pragma unroll
    for (int nt = 0; nt < 32; nt++) {
#pragma unroll
        for (int j = 0; j < 4; j++) acc[nt][j] *= 0.125f;
        mx0 = fmaxf(mx0, fmaxf(acc[nt][0], acc[nt][1]));
        mx1 = fmaxf(mx1, fmaxf(acc[nt][2], acc[nt][3]));
    }
    mx0 = fmaxf(mx0, __shfl_xor_sync(0xffffffffu, mx0, 1));
    mx0 = fmaxf(mx0, __shfl_xor_sync(0xffffffffu, mx0, 2));
    mx1 = fmaxf(mx1, __shfl_xor_sync(0xffffffffu, mx1, 1));
    mx1 = fmaxf(mx1, __shfl_xor_sync(0xffffffffu, mx1, 2));

    float s0 = 0.0f, s1 = 0.0f;
#pragma unroll
    for (int nt = 0; nt < 32; nt++) {
        acc[nt][0] = __expf(acc[nt][0] - mx0);
        acc[nt][1] = __expf(acc[nt][1] - mx0);
        acc[nt][2] = __expf(acc[nt][2] - mx1);
        acc[nt][3] = __expf(acc[nt][3] - mx1);
        s0 += acc[nt][0] + acc[nt][1];
        s1 += acc[nt][2] + acc[nt][3];
    }
    s0 += __shfl_xor_sync(0xffffffffu, s0, 1);
    s0 += __shfl_xor_sync(0xffffffffu, s0, 2);
    s1 += __shfl_xor_sync(0xffffffffu, s1, 1);
    s1 += __shfl_xor_sync(0xffffffffu, s1, 2);
    const float inv0 = 1.0f / s0;
    const float inv1 = 1.0f / s1;

    float oacc[8][4];
#pragma unroll
    for (int nt = 0; nt < 8; nt++)
#pragma unroll
        for (int j = 0; j < 4; j++) oacc[nt][j] = 0.0f;

#pragma unroll
    for (int kc = 0; kc < 16; kc++) {
        uint32_t af[4];
        af[0] = pack2(acc[2 * kc][0],     acc[2 * kc][1]);
        af[1] = pack2(acc[2 * kc][2],     acc[2 * kc][3]);
        af[2] = pack2(acc[2 * kc + 1][0], acc[2 * kc + 1][1]);
        af[3] = pack2(acc[2 * kc + 1][2], acc[2 * kc + 1][3]);
#pragma unroll
        for (int np = 0; np < 4; np++) {
            uint32_t r0, r1, r2, r3;
            LDMX4(r0, r1, r2, r3,
                  sptr(&Vs[(np * 16 + lr) * 264 + kc * 16 + lc * 8]));
            uint32_t b0[2] = { r0, r2 };
            uint32_t b1[2] = { r1, r3 };
            MMA16816(oacc[np * 2 + 0], af, b0);
            MMA16816(oacc[np * 2 + 1], af, b1);
        }
    }

    __half* Og = attn + ((size_t)b * LQ + q0 + warp * 16) * SEQ_D + h * HEAD;
#pragma unroll
    for (int nt = 0; nt < 8; nt++) {
        int c = nt * 8 + 2 * t4;
        float2 v0 = make_float2(oacc[nt][0] * inv0, oacc[nt][1] * inv0);
        float2 v1 = make_float2(oacc[nt][2] * inv1, oacc[nt][3] * inv1);
        *(__half2*)(Og + (size_t)g4 * SEQ_D + c)       = __float22half2_rn(v0);
        *(__half2*)(Og + (size_t)(g4 + 8) * SEQ_D + c) = __float22half2_rn(v1);
    }
}

// ---------------- fp32 -> fp16 elementwise ----------------
__global__ __launch_bounds__(256)
void f2h_kernel(const float* __restrict__ X, __half* __restrict__ Y)
{
    size_t s = (size_t)blockIdx.x * 256 + threadIdx.x;
    const float* p = X + s * 8;
    float4 v0 = *(const float4*)p, v1 = *(const float4*)(p + 4);
    uint4 u = { pack2(v0.x, v0.y), pack2(v0.z, v0.w),
                pack2(v1.x, v1.y), pack2(v1.z, v1.w) };
    *(uint4*)(Y + s * 8) = u;
}

// ---------------- weight transpose ----------------
__global__ __launch_bounds__(256)
void transpose_kernel(const float* __restrict__ W, __half* __restrict__ WT,
                      int K, int N)
{
    __shared__ float t[32][33];
    int n0 = blockIdx.x * 32, k0 = blockIdx.y * 32;
    int tx = threadIdx.x & 31, ty = threadIdx.x >> 5;
#pragma unroll
    for (int i = 0; i < 32; i += 8)
        t[ty + i][tx] = W[(size_t)(k0 + ty + i) * N + n0 + tx];
    __syncthreads();
#pragma unroll
    for (int i = 0; i < 32; i += 8)
        WT[(size_t)(n0 + ty + i) * K + k0 + tx] = __float2half_rn(t[tx][ty + i]);
}

// ---------------- V transpose per head (reads V half of KV) ----------------
__global__ __launch_bounds__(256)
void vt_kernel(const float* __restrict__ KV, __half* __restrict__ VT)
{
    __shared__ float t[32][33];
    int t0 = blockIdx.x * 32;
    int d0 = blockIdx.y * 32;
    int bh = blockIdx.z;
    int b = bh / NH, h = bh % NH;
    int tx = threadIdx.x & 31, ty = threadIdx.x >> 5;
#pragma unroll
    for (int i = 0; i < 32; i += 8)
        t[ty + i][tx] = KV[((size_t)b * TKV + t0 + ty + i) * (2 * SEQ_D)
                           + SEQ_D + h * HEAD + d0 + tx];
    __syncthreads();
#pragma unroll
    for (int i = 0; i < 32; i += 8)
        VT[((size_t)bh * HEAD + d0 + ty + i) * TKV + t0 + tx] =
            __float2half_rn(t[tx][ty + i]);
}

// ---------------- LayerNorm (templated in/out; ldx = input stride) -------
template <typename TIN, typename TOUT>
__global__ __launch_bounds__(256)
void ln_kernel(const TIN* __restrict__ X, const float* __restrict__ g,
               const float* __restrict__ b, TOUT* __restrict__ Y, int D, int ldx)
{
    long row = blockIdx.x;
    const float4* g4 = (const float4*)g;
    const float4* b4 = (const float4*)b;
    int n4 = D >> 2;

    float s = 0.0f, s2 = 0.0f;
    for (int i = threadIdx.x; i < n4; i += 256) {
        float4 v;
        if (sizeof(TIN) == 4) {
            v = ((const float4*)(const void*)(X + row * (long)ldx))[i];
        } else {
            uint2 u = ((const uint2*)(const void*)(X + row * (long)ldx))[i];
            float2 lo = __half22float2(*(__half2*)&u.x);
            float2 hi = __half22float2(*(__half2*)&u.y);
            v = make_float4(lo.x, lo.y, hi.x, hi.y);
        }
        s  += v.x + v.y + v.z + v.w;
        s2 += v.x * v.x + v.y * v.y + v.z * v.z + v.w * v.w;
    }
#pragma unroll
    for (int o = 16; o; o >>= 1) {
        s  += __shfl_xor_sync(0xffffffffu, s, o);
        s2 += __shfl_xor_sync(0xffffffffu, s2, o);
    }
    __shared__ float sh[16];
    int w = threadIdx.x >> 5, lane = threadIdx.x & 31;
    if (lane == 0) { sh[w] = s; sh[w + 8] = s2; }
    __syncthreads();
    if (threadIdx.x < 32) {
        float a = (threadIdx.x < 8) ? sh[threadIdx.x] : 0.0f;
        float c = (threadIdx.x < 8) ? sh[threadIdx.x + 8] : 0.0f;
#pragma unroll
        for (int o = 16; o; o >>= 1) {
            a += __shfl_xor_sync(0xffffffffu, a, o);
            c += __shfl_xor_sync(0xffffffffu, c, o);
        }
        if (threadIdx.x == 0) { sh[0] = a; sh[1] = c; }
    }
    __syncthreads();
    float invD = 1.0f / (float)D;
    float mu   = sh[0] * invD;
    float var  = sh[1] * invD - mu * mu;
    float rstd = rsqrtf(var + EPSF);

    for (int i = threadIdx.x; i < n4; i += 256) {
        float4 v;
        if (sizeof(TIN) == 4) {
            v = ((const float4*)(const void*)(X + row * (long)ldx))[i];
        } else {
            uint2 u = ((const uint2*)(const void*)(X + row * (long)ldx))[i];
            float2 lo = __half22float2(*(__half2*)&u.x);
            float2 hi = __half22float2(*(__half2*)&u.y);
            v = make_float4(lo.x, lo.y, hi.x, hi.y);
        }
        float4 gg = g4[i], bb = b4[i];
        v.x = (v.x - mu) * rstd * gg.x + bb.x;
        v.y = (v.y - mu) * rstd * gg.y + bb.y;
        v.z = (v.z - mu) * rstd * gg.z + bb.z;
        v.w = (v.w - mu) * rstd * gg.w + bb.w;
        if (sizeof(TOUT) == 4) {
            ((float4*)(void*)(Y + row * (long)D))[i] = v;
        } else {
            uint2 u = { pack2(v.x, v.y), pack2(v.z, v.w) };
            ((uint2*)(void*)(Y + row * (long)D))[i] = u;
        }
    }
}

// ---------------- launch ----------------
extern "C" void kernel_launch(void* const* d_in, const int* in_sizes, int n_in,
                              void* d_out, int out_size)
{
    const float* grid      = (const float*)d_in[0];
    const float* query_pos = (const float*)d_in[1];
    const float* Wq        = (const float*)d_in[2];
    const float* Wk        = (const float*)d_in[3];
    const float* Wv        = (const float*)d_in[4];
    const float* Wo        = (const float*)d_in[5];
    const float* lng_g     = (const float*)d_in[6];
    const float* lng_b     = (const float*)d_in[7];
    const float* lnq_g     = (const float*)d_in[8];
    const float* lnq_b     = (const float*)d_in[9];
    const float* lnm_g     = (const float*)d_in[10];
    const float* lnm_b     = (const float*)d_in[11];
    const float* W1        = (const float*)d_in[12];
    const float* b1        = (const float*)d_in[13];
    const float* W2        = (const float*)d_in[14];
    const float* b2        = (const float*)d_in[15];
    float* out = (float*)d_out;

    float *KV;
    __half *gridh, *Kn, *qn, *Qh, *attn, *xh, *xn, *hb;
    __half *WkvT, *WqT, *WoT, *W1T, *W2T, *VT;
    cudaGetSymbolAddress((void**)&gridh, g_gridh);
    cudaGetSymbolAddress((void**)&KV,   g_KV);
    cudaGetSymbolAddress((void**)&Kn,   g_Kn);
    cudaGetSymbolAddress((void**)&qn,   g_qn);
    cudaGetSymbolAddress((void**)&Qh,   g_Qh);
    cudaGetSymbolAddress((void**)&attn, g_attn);
    cudaGetSymbolAddress((void**)&xh,   g_xh);
    cudaGetSymbolAddress((void**)&xn,   g_xn);
    cudaGetSymbolAddress((void**)&hb,   g_h);
    cudaGetSymbolAddress((void**)&WkvT, g_WkvT);
    cudaGetSymbolAddress((void**)&WqT,  g_WqT);
    cudaGetSymbolAddress((void**)&WoT,  g_WoT);
    cudaGetSymbolAddress((void**)&W1T,  g_W1T);
    cudaGetSymbolAddress((void**)&W2T,  g_W2T);
    cudaGetSymbolAddress((void**)&VT,   g_VT);

    cudaFuncSetAttribute(fused_attn,
        cudaFuncAttributeMaxDynamicSharedMemorySize, FA_SMEM);
    cudaFuncSetAttribute(gemm_h<float, float, EPI_NONE>,
        cudaFuncAttributeMaxDynamicSharedMemorySize, GH_SMEM);
    cudaFuncSetAttribute(gemm_h<__half, float, EPI_NONE>,
        cudaFuncAttributeMaxDynamicSharedMemorySize, GH_SMEM);
    cudaFuncSetAttribute(gemm_h<__half, __half, EPI_RESID>,
        cudaFuncAttributeMaxDynamicSharedMemorySize, GH_SMEM);
    cudaFuncSetAttribute(gemm_h<__half, float, EPI_GELU_BIAS>,
        cudaFuncAttributeMaxDynamicSharedMemorySize, GH_SMEM);
    cudaFuncSetAttribute(gemm_h<float, __half, EPI_BIAS_RESID>,
        cudaFuncAttributeMaxDynamicSharedMemorySize, GH_SMEM);

    dim3 blk(256);
    const int MG = BB * TKV;       // 4096
    const int MQ = BB * LQ;        // 16384
    const int HD = MULT * SEQ_D;   // 4096

    // 0) fp16 conversions / transposes
    f2h_kernel<<<(MG * GRID_D) / (256 * 8), blk>>>(grid, gridh);
    transpose_kernel<<<dim3(SEQ_D / 32, GRID_D / 32), blk>>>(Wk, WkvT, GRID_D, SEQ_D);
    transpose_kernel<<<dim3(SEQ_D / 32, GRID_D / 32), blk>>>(
        Wv, WkvT + (size_t)SEQ_D * GRID_D, GRID_D, SEQ_D);
    transpose_kernel<<<dim3(SEQ_D / 32, POS_D / 32),  blk>>>(Wq, WqT, POS_D, SEQ_D);
    transpose_kernel<<<dim3(SEQ_D / 32, SEQ_D / 32),  blk>>>(Wo, WoT, SEQ_D, SEQ_D);
    transpose_kernel<<<dim3(HD / 32, SEQ_D / 32),     blk>>>(W1, W1T, SEQ_D, HD);
    transpose_kernel<<<dim3(SEQ_D / 32, HD / 32),     blk>>>(W2, W2T, HD, SEQ_D);

    // 1) KV = grid @ [Wk | Wv]  (merged, N=2048)
    gemm_h<float, float, EPI_NONE>
        <<<dim3(2 * SEQ_D / 128, MG / 128), blk, GH_SMEM>>>(
        gridh, WkvT, nullptr, nullptr, KV, MG, 2 * SEQ_D, GRID_D,
        GRID_D, GRID_D, 2 * SEQ_D, 1.0f);

    // 1b) VT from V half of KV
    vt_kernel<<<dim3(TKV / 32, HEAD / 32, BB * NH), blk>>>(KV, VT);

    // 2) Kn = LN(KV[:, :1024]) -> fp16 ; qn = LN(query_pos) -> fp16
    ln_kernel<float, __half><<<MG, 256>>>(KV, lng_g, lng_b, Kn, SEQ_D, 2 * SEQ_D);
    ln_kernel<float, __half><<<MQ, 256>>>(query_pos, lnq_g, lnq_b, qn, POS_D, POS_D);

    // 3) Qh = qn @ Wq -> fp16
    gemm_h<__half, float, EPI_NONE>
        <<<dim3(SEQ_D / 128, MQ / 128), blk, GH_SMEM>>>(
        qn, WqT, nullptr, nullptr, Qh, MQ, SEQ_D, POS_D,
        POS_D, POS_D, SEQ_D, 1.0f);

    // 4-6) fused attention -> attn fp16
    fused_attn<<<dim3(LQ / 128, BB * NH), blk, FA_SMEM>>>(Qh, Kn, VT, attn);

    // 7) xh = Qh + attn @ Wo  (fp16 out)
    gemm_h<__half, __half, EPI_RESID>
        <<<dim3(SEQ_D / 128, MQ / 128), blk, GH_SMEM>>>(
        attn, WoT, nullptr, Qh, xh, MQ, SEQ_D, SEQ_D,
        SEQ_D, SEQ_D, SEQ_D, 1.0f);

    // 8) xn = LN(xh) -> fp16
    ln_kernel<__half, __half><<<MQ, 256>>>(xh, lnm_g, lnm_b, xn, SEQ_D, SEQ_D);

    // 9) hb = gelu(xn @ W1 + b1) -> fp16
    gemm_h<__half, float, EPI_GELU_BIAS>
        <<<dim3(HD / 128, MQ / 128), blk, GH_SMEM>>>(
        xn, W1T, b1, nullptr, hb, MQ, HD, SEQ_D,
        SEQ_D, SEQ_D, HD, 1.0f);

    // 10) out = xh + hb @ W2 + b2  (fp32 out)
    gemm_h<float, __half, EPI_BIAS_RESID>
        <<<dim3(SEQ_D / 128, MQ / 128), blk, GH_SMEM>>>(
        hb, W2T, b2, xh, out, MQ, SEQ_D, HD,
        HD, HD, SEQ_D, 1.0f);
}